// round 9
// baseline (speedup 1.0000x reference)
#include <cuda_runtime.h>
#include <cuda_fp16.h>
#include <cuda_bf16.h>

namespace {
constexpr int kNUser = 50000;
constexpr int kN     = 80000;      // total nodes
constexpr int kE     = 1000000;    // 2 * NNZ symmetric edges
constexpr int kD     = 64;
constexpr int kChunk = 1024;
constexpr int kNChunk = (kN + kChunk - 1) / kChunk;   // 79
}

// ---------------- device scratch (static, no allocation) ----------------
__device__ float g_A[kE * 4];         // routing logits, CSR-slot order
__device__ float g_normA[kE * 4];     // softmax(A), CSR-slot order
__device__ float g_buf0[kN * kD];     // initial ego (layer-0 input; never overwritten)
__device__ float g_buf1[kN * kD];     // layer-0 output = layer-1 input
__device__ float g_egoS[kN * kD];     // layer ego prescaled by current dinv (fp32)
__device__ uint4 g_TnV[kN * 8];       // tanh(normalized tail chunks), fp16, 128B/node
__device__ float g_dinvA[kN * 4];     // 1/sqrt(degree-weight), ping
__device__ float g_dinvB[kN * 4];     // pong
__device__ int   g_ptr[kN + 1];       // CSR row pointers (by head)
__device__ int   g_cnt[kN];           // histogram / fill counters
__device__ int   g_csr_t[kE];         // tail node per CSR slot
__device__ int   g_bsum[kNChunk];     // per-chunk sums for multi-block scan

__device__ __forceinline__ unsigned pack_h2(float a, float b) {
    __half2 h = __floats2half2_rn(a, b);
    return *reinterpret_cast<unsigned*>(&h);
}

// ---------------- init ----------------
__global__ void k_init_ego(const float* __restrict__ user, const float* __restrict__ item) {
    int i = blockIdx.x * blockDim.x + threadIdx.x;
    if (i >= kN * kD) return;
    g_buf0[i] = (i < kNUser * kD) ? user[i] : item[i - kNUser * kD];
}

__global__ void k_zero_cnt() {
    int i = blockIdx.x * blockDim.x + threadIdx.x;
    if (i < kN) g_cnt[i] = 0;
}

// A=1, normA=0.25 everywhere (slot-independent) -- coalesced
__global__ void k_init_A() {
    int i = blockIdx.x * blockDim.x + threadIdx.x;
    if (i >= kE) return;
    reinterpret_cast<float4*>(g_A)[i]     = make_float4(1.f, 1.f, 1.f, 1.f);
    reinterpret_cast<float4*>(g_normA)[i] = make_float4(.25f, .25f, .25f, .25f);
}

// ---------------- CSR build ----------------
__global__ void k_count(const int* __restrict__ h) {
    int e = blockIdx.x * blockDim.x + threadIdx.x;
    if (e >= kE) return;
    atomicAdd(&g_cnt[h[e]], 1);
}

__global__ void k_chunk_reduce() {            // kNChunk blocks x 256
    __shared__ int wsum[8];
    const int lane = threadIdx.x & 31, wrp = threadIdx.x >> 5;
    int base = blockIdx.x * kChunk + (int)threadIdx.x * 4;
    int s = 0;
    #pragma unroll
    for (int k = 0; k < 4; k++) { int i = base + k; if (i < kN) s += g_cnt[i]; }
    #pragma unroll
    for (int o = 16; o >= 1; o >>= 1) s += __shfl_xor_sync(0xffffffffu, s, o);
    if (lane == 0) wsum[wrp] = s;
    __syncthreads();
    if (threadIdx.x == 0) {
        int t = 0;
        #pragma unroll
        for (int k = 0; k < 8; k++) t += wsum[k];
        g_bsum[blockIdx.x] = t;
    }
}

__global__ void k_bsum_scan() {               // 1 block x 32
    const int lane = threadIdx.x;
    int carry = 0;
    for (int base = 0; base < kNChunk; base += 32) {
        int i = base + lane;
        int v = (i < kNChunk) ? g_bsum[i] : 0;
        int x = v;
        #pragma unroll
        for (int o = 1; o < 32; o <<= 1) {
            int y = __shfl_up_sync(0xffffffffu, x, o);
            if (lane >= o) x += y;
        }
        if (i < kNChunk) g_bsum[i] = carry + x - v;     // exclusive
        carry += __shfl_sync(0xffffffffu, x, 31);
    }
    if (lane == 0) g_ptr[kN] = carry;
}

__global__ void k_chunk_scan() {              // kNChunk blocks x 256
    __shared__ int wsum[8];
    const int lane = threadIdx.x & 31, wrp = threadIdx.x >> 5;
    int base = blockIdx.x * kChunk + (int)threadIdx.x * 4;
    int v0 = 0, v1 = 0, v2 = 0, v3 = 0;
    if (base + 3 < kN) {
        int4 v = *reinterpret_cast<const int4*>(&g_cnt[base]);
        v0 = v.x; v1 = v.y; v2 = v.z; v3 = v.w;
    } else {
        if (base + 0 < kN) v0 = g_cnt[base + 0];
        if (base + 1 < kN) v1 = g_cnt[base + 1];
        if (base + 2 < kN) v2 = g_cnt[base + 2];
        if (base + 3 < kN) v3 = g_cnt[base + 3];
    }
    int tot = v0 + v1 + v2 + v3;
    int x = tot;
    #pragma unroll
    for (int o = 1; o < 32; o <<= 1) {
        int y = __shfl_up_sync(0xffffffffu, x, o);
        if (lane >= o) x += y;
    }
    if (lane == 31) wsum[wrp] = x;
    __syncthreads();
    if (wrp == 0 && lane < 8) {
        int s = wsum[lane], xs = s;
        #pragma unroll
        for (int o = 1; o < 8; o <<= 1) {
            int y = __shfl_up_sync(0xffu, xs, o);
            if (lane >= o) xs += y;
        }
        wsum[lane] = xs - s;
    }
    __syncthreads();
    int ex = g_bsum[blockIdx.x] + wsum[wrp] + (x - tot);
    if (base + 0 < kN) { g_ptr[base + 0] = ex;                g_cnt[base + 0] = 0; }
    if (base + 1 < kN) { g_ptr[base + 1] = ex + v0;           g_cnt[base + 1] = 0; }
    if (base + 2 < kN) { g_ptr[base + 2] = ex + v0 + v1;      g_cnt[base + 2] = 0; }
    if (base + 3 < kN) { g_ptr[base + 3] = ex + v0 + v1 + v2; g_cnt[base + 3] = 0; }
}

// fill CSR (tail ids only; A/normA initialized coalesced elsewhere)
__global__ void k_fill(const int* __restrict__ h, const int* __restrict__ t) {
    int e = blockIdx.x * blockDim.x + threadIdx.x;
    if (e >= kE) return;
    int hn   = h[e];
    int slot = g_ptr[hn] + atomicAdd(&g_cnt[hn], 1);
    g_csr_t[slot] = t[e];
}

// initial dinv: normA = 0.25 everywhere -> dval = 0.25 * deg
__global__ void k_dinv0() {
    int n = blockIdx.x * blockDim.x + threadIdx.x;
    if (n >= kN) return;
    float dval = 0.25f * (float)(g_ptr[n + 1] - g_ptr[n]);
    float di = rsqrtf(fmaxf(dval, 1e-8f));
    reinterpret_cast<float4*>(g_dinvA)[n] = make_float4(di, di, di, di);
}

// ---------------- per-layer: tanh(normalized tail chunks)->fp16 + egoS = ego*dinvA ----------------
__global__ void k_tail(int sel) {
    const float* ego = sel ? g_buf1 : g_buf0;
    int i = blockIdx.x * blockDim.x + threadIdx.x;   // (node, factor)
    if (i >= kN * 4) return;
    const float4* src = reinterpret_cast<const float4*>(ego) + i * 4;
    float4 v0 = src[0], v1 = src[1], v2 = src[2], v3 = src[3];
    float ss = v0.x*v0.x + v0.y*v0.y + v0.z*v0.z + v0.w*v0.w
             + v1.x*v1.x + v1.y*v1.y + v1.z*v1.z + v1.w*v1.w
             + v2.x*v2.x + v2.y*v2.y + v2.z*v2.z + v2.w*v2.w
             + v3.x*v3.x + v3.y*v3.y + v3.z*v3.z + v3.w*v3.w;
    float inv = 1.0f / fmaxf(sqrtf(ss), 1e-12f);
    uint4 u0, u1;
    u0.x = pack_h2(tanhf(v0.x*inv), tanhf(v0.y*inv));
    u0.y = pack_h2(tanhf(v0.z*inv), tanhf(v0.w*inv));
    u0.z = pack_h2(tanhf(v1.x*inv), tanhf(v1.y*inv));
    u0.w = pack_h2(tanhf(v1.z*inv), tanhf(v1.w*inv));
    u1.x = pack_h2(tanhf(v2.x*inv), tanhf(v2.y*inv));
    u1.y = pack_h2(tanhf(v2.z*inv), tanhf(v2.w*inv));
    u1.z = pack_h2(tanhf(v3.x*inv), tanhf(v3.y*inv));
    u1.w = pack_h2(tanhf(v3.z*inv), tanhf(v3.w*inv));
    g_TnV[i * 2]     = u0;
    g_TnV[i * 2 + 1] = u1;
    float di = g_dinvA[i];
    float4* ds = reinterpret_cast<float4*>(g_egoS) + i * 4;
    ds[0] = make_float4(v0.x*di, v0.y*di, v0.z*di, v0.w*di);
    ds[1] = make_float4(v1.x*di, v1.y*di, v1.z*di, v1.w*di);
    ds[2] = make_float4(v2.x*di, v2.y*di, v2.z*di, v2.w*di);
    ds[3] = make_float4(v3.x*di, v3.y*di, v3.z*di, v3.w*di);
}

// ---------------- between iterations: egoS = ego * dinvB (coalesced) ----------------
__global__ void k_rescale(int sel) {
    const float* ego = sel ? g_buf1 : g_buf0;
    int i = blockIdx.x * blockDim.x + threadIdx.x;   // (node, factor)
    if (i >= kN * 4) return;
    const float4* src = reinterpret_cast<const float4*>(ego) + i * 4;
    float di = g_dinvB[i];
    float4* ds = reinterpret_cast<float4*>(g_egoS) + i * 4;
    float4 v0 = src[0], v1 = src[1], v2 = src[2], v3 = src[3];
    ds[0] = make_float4(v0.x*di, v0.y*di, v0.z*di, v0.w*di);
    ds[1] = make_float4(v1.x*di, v1.y*di, v1.z*di, v1.w*di);
    ds[2] = make_float4(v2.x*di, v2.y*di, v2.z*di, v2.w*di);
    ds[3] = make_float4(v3.x*di, v3.y*di, v3.z*di, v3.w*di);
}

// ---------------- fused iteration ----------------
// one warp per node. MP: lane owns dims [2l,2l+1], factor f = lane>>3,
// smem-staged edge weights + cooperative staging of each edge's fp16 Tn row
// into smem (first 32 edges). Routing: half-warp per edge, Tn read from smem
// (global fallback for edges >= 32).
// mode: 0 = routing, fe NOT written; 1 = routing + fe write; 2 = final output.
__global__ void __launch_bounds__(256) k_fused(
        int sel_in, int dsel, int mode, float* __restrict__ out)
{
    __shared__ int    sm_t[8][32];
    __shared__ float  sm_wT[8][4][33];
    __shared__ float2 sm_h[8][32];        // normalized head (64 floats / warp)
    __shared__ unsigned sm_tn[8][32][32]; // staged fp16 Tn rows: 32 edges x 128B / warp

    const int warp = threadIdx.x >> 5;
    const int lane = threadIdx.x & 31;
    const int w = blockIdx.x * 8 + warp;
    const int f = lane >> 3;

    const float*  ego    = sel_in ? g_buf1 : g_buf0;
    float*        fe     = sel_in ? g_buf0 : g_buf1;   // only written in mode 1 (sel_in=0)
    const float2* egoS   = reinterpret_cast<const float2*>(g_egoS);
    const float4* dinvC  = reinterpret_cast<const float4*>(dsel ? g_dinvB : g_dinvA);
    float4*       dinvN  = reinterpret_cast<float4*>(dsel ? g_dinvA : g_dinvB);
    const float4* normA  = reinterpret_cast<const float4*>(g_normA);
    const unsigned* TnU  = reinterpret_cast<const unsigned*>(g_TnV);

    const int s = g_ptr[w], e = g_ptr[w + 1];
    const bool rout = (mode != 2);

    // ---- message passing (+ Tn staging for routing) ----
    float2 acc = make_float2(0.f, 0.f);
    for (int base = s; base < e; base += 32) {
        int j = base + lane;
        bool valid = j < e;
        int t = valid ? g_csr_t[j] : 0;
        float4 na = valid ? normA[j] : make_float4(0.f, 0.f, 0.f, 0.f);
        sm_t[warp][lane] = t;
        sm_wT[warp][0][lane] = na.x;
        sm_wT[warp][1][lane] = na.y;
        sm_wT[warp][2][lane] = na.z;
        sm_wT[warp][3][lane] = na.w;
        __syncwarp();
        int cnt = min(32, e - base);
        if (rout && base == s) {
            // fused gather: egoS row for MP + Tn row staged to smem
            #pragma unroll 4
            for (int k = 0; k < cnt; k++) {
                int   tk = sm_t[warp][k];
                float wk = sm_wT[warp][f][k];
                float2 ev = egoS[tk * 32 + lane];
                sm_tn[warp][k][lane] = TnU[tk * 32 + lane];
                acc.x += wk * ev.x;
                acc.y += wk * ev.y;
            }
        } else {
            #pragma unroll 8
            for (int k = 0; k < cnt; k++) {
                int   tk = sm_t[warp][k];
                float wk = sm_wT[warp][f][k];
                float2 ev = egoS[tk * 32 + lane];
                acc.x += wk * ev.x;
                acc.y += wk * ev.y;
            }
        }
        __syncwarp();
    }
    {
        float4 dh = dinvC[w];
        float ds = (f == 0) ? dh.x : (f == 1) ? dh.y : (f == 2) ? dh.z : dh.w;
        acc.x *= ds; acc.y *= ds;
    }

    if (mode == 2) {
        // final: out = (initial_ego(buf0) + layer1_input(buf1) + fe)/3
        float2 a = reinterpret_cast<const float2*>(g_buf0 + w * kD)[lane];
        float2 b = reinterpret_cast<const float2*>(ego + w * kD)[lane];
        float2 o;
        o.x = (a.x + b.x + acc.x) * (1.0f / 3.0f);
        o.y = (a.y + b.y + acc.y) * (1.0f / 3.0f);
        reinterpret_cast<float2*>(out + w * kD)[lane] = o;
        return;
    }

    if (mode == 1)
        reinterpret_cast<float2*>(fe + w * kD)[lane] = acc;

    // ---- head inverse norm (per 8-lane group = one factor) ----
    float ss = acc.x * acc.x + acc.y * acc.y;
    #pragma unroll
    for (int o = 4; o >= 1; o >>= 1) ss += __shfl_xor_sync(0xffffffffu, ss, o);
    const float hinv = 1.0f / fmaxf(sqrtf(ss), 1e-12f);
    sm_h[warp][lane] = make_float2(acc.x * hinv, acc.y * hinv);
    __syncwarp();

    // ---- routing: half-warp per edge, Tn from smem (global fallback >=32) ----
    // lane = half*16 + r; r owns dims [4r, 4r+3]; factor fr = r>>2.
    const float4* hp4 = reinterpret_cast<const float4*>(&sm_h[warp][0]);
    const int half = lane >> 4;
    const int r    = lane & 15;
    const int fr   = r >> 2;
    const bool fl  = (r & 3) == 0;    // factor-leader lane
    float dv = 0.f;
    for (int b = s; b < e; b += 2) {
        int j = b + half;
        bool valid = j < e;
        int idx = j - s;
        uint2 tv = make_uint2(0u, 0u);
        if (valid) {
            if (idx < 32) {
                tv.x = sm_tn[warp][idx][2 * r];
                tv.y = sm_tn[warp][idx][2 * r + 1];
            } else {
                int t = g_csr_t[j];
                tv = reinterpret_cast<const uint2*>(g_TnV)[t * 16 + r];
            }
        }
        float4 hv = hp4[r];
        float2 t0 = __half22float2(*reinterpret_cast<__half2*>(&tv.x));
        float2 t1 = __half22float2(*reinterpret_cast<__half2*>(&tv.y));
        float p = hv.x*t0.x + hv.y*t0.y + hv.z*t1.x + hv.w*t1.y;
        p += __shfl_xor_sync(0xffffffffu, p, 1);
        p += __shfl_xor_sync(0xffffffffu, p, 2);
        // lanes r%4==0 hold q for factor fr of edge j
        float An = 0.f;
        if (fl && valid) An = g_A[j * 4 + fr] + p;
        float m = fmaxf(An, __shfl_xor_sync(0xffffffffu, An, 4));
        m = fmaxf(m, __shfl_xor_sync(0xffffffffu, m, 8));
        float ex = __expf(An - m);
        float sm = ex + __shfl_xor_sync(0xffffffffu, ex, 4);
        sm += __shfl_xor_sync(0xffffffffu, sm, 8);
        if (fl && valid) {
            float nA = ex / sm;
            g_A[j * 4 + fr]     = An;
            g_normA[j * 4 + fr] = nA;
            dv += nA;
        }
    }
    // combine halves: lanes {0,4,8,12} then hold total dval per factor
    dv += __shfl_xor_sync(0xffffffffu, dv, 16);
    float d1 = __shfl_sync(0xffffffffu, dv, 4);
    float d2 = __shfl_sync(0xffffffffu, dv, 8);
    float d3 = __shfl_sync(0xffffffffu, dv, 12);
    if (lane == 0) {
        dinvN[w] = make_float4(rsqrtf(fmaxf(dv, 1e-8f)),
                               rsqrtf(fmaxf(d1, 1e-8f)),
                               rsqrtf(fmaxf(d2, 1e-8f)),
                               rsqrtf(fmaxf(d3, 1e-8f)));
    }
}

// ---------------- host driver ----------------
extern "C" void kernel_launch(void* const* d_in, const int* in_sizes, int n_in,
                              void* d_out, int out_size) {
    const float* user = (const float*)d_in[0];
    const float* item = (const float*)d_in[1];
    const int*   hl   = (const int*)d_in[2];
    const int*   tl   = (const int*)d_in[3];
    float* out = (float*)d_out;

    const int TB = 256;
    k_init_ego<<<(kN * kD + TB - 1) / TB, TB>>>(user, item);
    k_zero_cnt<<<(kN + TB - 1) / TB, TB>>>();
    k_init_A<<<(kE + TB - 1) / TB, TB>>>();
    k_count<<<(kE + TB - 1) / TB, TB>>>(hl);
    k_chunk_reduce<<<kNChunk, TB>>>();
    k_bsum_scan<<<1, 32>>>();
    k_chunk_scan<<<kNChunk, TB>>>();
    k_fill<<<(kE + TB - 1) / TB, TB>>>(hl, tl);
    k_dinv0<<<(kN + TB - 1) / TB, TB>>>();

    const int FG = kN / 8;   // 8 warps / block
    const int RG = (kN * 4 + TB - 1) / TB;
    // layer 0: ego=buf0 -> fe=buf1
    k_tail<<<RG, TB>>>(0);                      // Tn(buf0) fp16, egoS = buf0*dinvA(init)
    k_fused<<<FG, TB>>>(0, 0, 0, out);          // it0: reads dinvA, writes dinvB; no fe
    k_rescale<<<RG, TB>>>(0);                   // egoS = buf0*dinvB
    k_fused<<<FG, TB>>>(0, 1, 1, out);          // it1: reads dinvB, writes dinvA; fe->buf1
    // layer 1: ego=buf1 -> out
    k_tail<<<RG, TB>>>(1);                      // Tn(buf1) fp16, egoS = buf1*dinvA
    k_fused<<<FG, TB>>>(1, 0, 0, out);          // it0: reads dinvA, writes dinvB; no fe
    k_rescale<<<RG, TB>>>(1);                   // egoS = buf1*dinvB
    k_fused<<<FG, TB>>>(1, 1, 2, out);          // final: reads dinvB, no routing
    (void)in_sizes; (void)n_in; (void)out_size;
}

// round 10
// speedup vs baseline: 1.3729x; 1.3729x over previous
#include <cuda_runtime.h>
#include <cuda_fp16.h>
#include <cuda_bf16.h>

namespace {
constexpr int kNUser = 50000;
constexpr int kN     = 80000;      // total nodes
constexpr int kE     = 1000000;    // 2 * NNZ symmetric edges
constexpr int kD     = 64;
constexpr int kChunk = 1024;
constexpr int kNChunk = (kN + kChunk - 1) / kChunk;   // 79
}

// ---------------- device scratch (static, no allocation) ----------------
__device__ float g_A[kE * 4];         // routing logits, CSR-slot order
__device__ float g_normA[kE * 4];     // softmax(A), CSR-slot order
__device__ float g_buf0[kN * kD];     // initial ego (layer-0 input; never overwritten)
__device__ float g_buf1[kN * kD];     // layer-0 output = layer-1 input
__device__ float g_egoS[kN * kD];     // layer ego prescaled by current dinv (fp32)
__device__ uint4 g_TnV[kN * 8];       // tanh(normalized tail chunks), fp16, 128B/node
__device__ float g_dinvA[kN * 4];     // 1/sqrt(degree-weight), ping
__device__ float g_dinvB[kN * 4];     // pong
__device__ int   g_ptr[kN + 1];       // CSR row pointers (by head)
__device__ int   g_cnt[kN];           // histogram / fill counters
__device__ int   g_csr_t[kE];         // tail node per CSR slot
__device__ int   g_bsum[kNChunk];     // per-chunk sums for multi-block scan

__device__ __forceinline__ unsigned pack_h2(float a, float b) {
    __half2 h = __floats2half2_rn(a, b);
    return *reinterpret_cast<unsigned*>(&h);
}

// ---------------- init ----------------
__global__ void k_init_ego(const float* __restrict__ user, const float* __restrict__ item) {
    int i = blockIdx.x * blockDim.x + threadIdx.x;
    if (i >= kN * kD) return;
    g_buf0[i] = (i < kNUser * kD) ? user[i] : item[i - kNUser * kD];
}

__global__ void k_zero_cnt() {
    int i = blockIdx.x * blockDim.x + threadIdx.x;
    if (i < kN) g_cnt[i] = 0;
}

// ---------------- CSR build ----------------
__global__ void k_count(const int* __restrict__ h) {
    int e = blockIdx.x * blockDim.x + threadIdx.x;
    if (e >= kE) return;
    atomicAdd(&g_cnt[h[e]], 1);
}

__global__ void k_chunk_reduce() {            // kNChunk blocks x 256
    __shared__ int wsum[8];
    const int lane = threadIdx.x & 31, wrp = threadIdx.x >> 5;
    int base = blockIdx.x * kChunk + (int)threadIdx.x * 4;
    int s = 0;
    #pragma unroll
    for (int k = 0; k < 4; k++) { int i = base + k; if (i < kN) s += g_cnt[i]; }
    #pragma unroll
    for (int o = 16; o >= 1; o >>= 1) s += __shfl_xor_sync(0xffffffffu, s, o);
    if (lane == 0) wsum[wrp] = s;
    __syncthreads();
    if (threadIdx.x == 0) {
        int t = 0;
        #pragma unroll
        for (int k = 0; k < 8; k++) t += wsum[k];
        g_bsum[blockIdx.x] = t;
    }
}

__global__ void k_bsum_scan() {               // 1 block x 32
    const int lane = threadIdx.x;
    int carry = 0;
    for (int base = 0; base < kNChunk; base += 32) {
        int i = base + lane;
        int v = (i < kNChunk) ? g_bsum[i] : 0;
        int x = v;
        #pragma unroll
        for (int o = 1; o < 32; o <<= 1) {
            int y = __shfl_up_sync(0xffffffffu, x, o);
            if (lane >= o) x += y;
        }
        if (i < kNChunk) g_bsum[i] = carry + x - v;     // exclusive
        carry += __shfl_sync(0xffffffffu, x, 31);
    }
    if (lane == 0) g_ptr[kN] = carry;
}

__global__ void k_chunk_scan() {              // kNChunk blocks x 256
    __shared__ int wsum[8];
    const int lane = threadIdx.x & 31, wrp = threadIdx.x >> 5;
    int base = blockIdx.x * kChunk + (int)threadIdx.x * 4;
    int v0 = 0, v1 = 0, v2 = 0, v3 = 0;
    if (base + 3 < kN) {
        int4 v = *reinterpret_cast<const int4*>(&g_cnt[base]);
        v0 = v.x; v1 = v.y; v2 = v.z; v3 = v.w;
    } else {
        if (base + 0 < kN) v0 = g_cnt[base + 0];
        if (base + 1 < kN) v1 = g_cnt[base + 1];
        if (base + 2 < kN) v2 = g_cnt[base + 2];
        if (base + 3 < kN) v3 = g_cnt[base + 3];
    }
    int tot = v0 + v1 + v2 + v3;
    int x = tot;
    #pragma unroll
    for (int o = 1; o < 32; o <<= 1) {
        int y = __shfl_up_sync(0xffffffffu, x, o);
        if (lane >= o) x += y;
    }
    if (lane == 31) wsum[wrp] = x;
    __syncthreads();
    if (wrp == 0 && lane < 8) {
        int s = wsum[lane], xs = s;
        #pragma unroll
        for (int o = 1; o < 8; o <<= 1) {
            int y = __shfl_up_sync(0xffu, xs, o);
            if (lane >= o) xs += y;
        }
        wsum[lane] = xs - s;
    }
    __syncthreads();
    int ex = g_bsum[blockIdx.x] + wsum[wrp] + (x - tot);
    if (base + 0 < kN) { g_ptr[base + 0] = ex;                g_cnt[base + 0] = 0; }
    if (base + 1 < kN) { g_ptr[base + 1] = ex + v0;           g_cnt[base + 1] = 0; }
    if (base + 2 < kN) { g_ptr[base + 2] = ex + v0 + v1;      g_cnt[base + 2] = 0; }
    if (base + 3 < kN) { g_ptr[base + 3] = ex + v0 + v1 + v2; g_cnt[base + 3] = 0; }
}

// fill CSR + initialize A=1, normA=0.25 in slot order (R7 configuration)
__global__ void k_fill(const int* __restrict__ h, const int* __restrict__ t) {
    int e = blockIdx.x * blockDim.x + threadIdx.x;
    if (e >= kE) return;
    int hn   = h[e];
    int slot = g_ptr[hn] + atomicAdd(&g_cnt[hn], 1);
    g_csr_t[slot] = t[e];
    reinterpret_cast<float4*>(g_A)[slot]     = make_float4(1.f, 1.f, 1.f, 1.f);
    reinterpret_cast<float4*>(g_normA)[slot] = make_float4(.25f, .25f, .25f, .25f);
}

// initial dinv: normA = 0.25 everywhere -> dval = 0.25 * deg
__global__ void k_dinv0() {
    int n = blockIdx.x * blockDim.x + threadIdx.x;
    if (n >= kN) return;
    float dval = 0.25f * (float)(g_ptr[n + 1] - g_ptr[n]);
    float di = rsqrtf(fmaxf(dval, 1e-8f));
    reinterpret_cast<float4*>(g_dinvA)[n] = make_float4(di, di, di, di);
}

// ---------------- per-layer: tanh(normalized tail chunks)->fp16 + egoS = ego*dinvA ----------------
__global__ void k_tail(int sel) {
    const float* ego = sel ? g_buf1 : g_buf0;
    int i = blockIdx.x * blockDim.x + threadIdx.x;   // (node, factor)
    if (i >= kN * 4) return;
    const float4* src = reinterpret_cast<const float4*>(ego) + i * 4;
    float4 v0 = src[0], v1 = src[1], v2 = src[2], v3 = src[3];
    float ss = v0.x*v0.x + v0.y*v0.y + v0.z*v0.z + v0.w*v0.w
             + v1.x*v1.x + v1.y*v1.y + v1.z*v1.z + v1.w*v1.w
             + v2.x*v2.x + v2.y*v2.y + v2.z*v2.z + v2.w*v2.w
             + v3.x*v3.x + v3.y*v3.y + v3.z*v3.z + v3.w*v3.w;
    float inv = 1.0f / fmaxf(sqrtf(ss), 1e-12f);
    uint4 u0, u1;
    u0.x = pack_h2(tanhf(v0.x*inv), tanhf(v0.y*inv));
    u0.y = pack_h2(tanhf(v0.z*inv), tanhf(v0.w*inv));
    u0.z = pack_h2(tanhf(v1.x*inv), tanhf(v1.y*inv));
    u0.w = pack_h2(tanhf(v1.z*inv), tanhf(v1.w*inv));
    u1.x = pack_h2(tanhf(v2.x*inv), tanhf(v2.y*inv));
    u1.y = pack_h2(tanhf(v2.z*inv), tanhf(v2.w*inv));
    u1.z = pack_h2(tanhf(v3.x*inv), tanhf(v3.y*inv));
    u1.w = pack_h2(tanhf(v3.z*inv), tanhf(v3.w*inv));
    g_TnV[i * 2]     = u0;
    g_TnV[i * 2 + 1] = u1;
    float di = g_dinvA[i];
    float4* ds = reinterpret_cast<float4*>(g_egoS) + i * 4;
    ds[0] = make_float4(v0.x*di, v0.y*di, v0.z*di, v0.w*di);
    ds[1] = make_float4(v1.x*di, v1.y*di, v1.z*di, v1.w*di);
    ds[2] = make_float4(v2.x*di, v2.y*di, v2.z*di, v2.w*di);
    ds[3] = make_float4(v3.x*di, v3.y*di, v3.z*di, v3.w*di);
}

// ---------------- between iterations: egoS = ego * dinvB (coalesced) ----------------
__global__ void k_rescale(int sel) {
    const float* ego = sel ? g_buf1 : g_buf0;
    int i = blockIdx.x * blockDim.x + threadIdx.x;   // (node, factor)
    if (i >= kN * 4) return;
    const float4* src = reinterpret_cast<const float4*>(ego) + i * 4;
    float di = g_dinvB[i];
    float4* ds = reinterpret_cast<float4*>(g_egoS) + i * 4;
    float4 v0 = src[0], v1 = src[1], v2 = src[2], v3 = src[3];
    ds[0] = make_float4(v0.x*di, v0.y*di, v0.z*di, v0.w*di);
    ds[1] = make_float4(v1.x*di, v1.y*di, v1.z*di, v1.w*di);
    ds[2] = make_float4(v2.x*di, v2.y*di, v2.z*di, v2.w*di);
    ds[3] = make_float4(v3.x*di, v3.y*di, v3.z*di, v3.w*di);
}

// ---------------- fused iteration ----------------
// one warp per node. MP: lane owns dims [2l,2l+1], factor f = lane>>3,
// smem-staged edge weights (identical to R7).
// Routing: LANE-PER-EDGE, per-lane softmax (no shfl in loop); Tn fp16 row
// = 128B = 1 line/edge, read as 8 uint4 (L1 hits after first).
// mode: 0 = routing, fe NOT written; 1 = routing + fe write; 2 = final output.
__global__ void __launch_bounds__(256) k_fused(
        int sel_in, int dsel, int mode, float* __restrict__ out)
{
    __shared__ int    sm_t[8][32];
    __shared__ float  sm_wT[8][4][33];
    __shared__ float2 sm_h[8][32];      // normalized head (64 floats / warp)

    const int warp = threadIdx.x >> 5;
    const int lane = threadIdx.x & 31;
    const int w = blockIdx.x * 8 + warp;
    const int f = lane >> 3;

    const float*  ego    = sel_in ? g_buf1 : g_buf0;
    float*        fe     = sel_in ? g_buf0 : g_buf1;   // only written in mode 1 (sel_in=0)
    const float2* egoS   = reinterpret_cast<const float2*>(g_egoS);
    const float4* dinvC  = reinterpret_cast<const float4*>(dsel ? g_dinvB : g_dinvA);
    float4*       dinvN  = reinterpret_cast<float4*>(dsel ? g_dinvA : g_dinvB);
    const float4* normA  = reinterpret_cast<const float4*>(g_normA);
    float4*       normAo = reinterpret_cast<float4*>(g_normA);
    float4*       Ap     = reinterpret_cast<float4*>(g_A);

    const int s = g_ptr[w], e = g_ptr[w + 1];

    // ---- message passing (identical to R7) ----
    float2 acc = make_float2(0.f, 0.f);
    for (int base = s; base < e; base += 32) {
        int j = base + lane;
        bool valid = j < e;
        int t = valid ? g_csr_t[j] : 0;
        float4 na = valid ? normA[j] : make_float4(0.f, 0.f, 0.f, 0.f);
        sm_t[warp][lane] = t;
        sm_wT[warp][0][lane] = na.x;
        sm_wT[warp][1][lane] = na.y;
        sm_wT[warp][2][lane] = na.z;
        sm_wT[warp][3][lane] = na.w;
        __syncwarp();
        int cnt = min(32, e - base);
        #pragma unroll 8
        for (int k = 0; k < cnt; k++) {
            int   tk = sm_t[warp][k];
            float wk = sm_wT[warp][f][k];
            float2 ev = egoS[tk * 32 + lane];
            acc.x += wk * ev.x;
            acc.y += wk * ev.y;
        }
        __syncwarp();
    }
    {
        float4 dh = dinvC[w];
        float ds = (f == 0) ? dh.x : (f == 1) ? dh.y : (f == 2) ? dh.z : dh.w;
        acc.x *= ds; acc.y *= ds;
    }

    if (mode == 2) {
        // final: out = (initial_ego(buf0) + layer1_input(buf1) + fe)/3
        float2 a = reinterpret_cast<const float2*>(g_buf0 + w * kD)[lane];
        float2 b = reinterpret_cast<const float2*>(ego + w * kD)[lane];
        float2 o;
        o.x = (a.x + b.x + acc.x) * (1.0f / 3.0f);
        o.y = (a.y + b.y + acc.y) * (1.0f / 3.0f);
        reinterpret_cast<float2*>(out + w * kD)[lane] = o;
        return;
    }

    if (mode == 1)
        reinterpret_cast<float2*>(fe + w * kD)[lane] = acc;

    // ---- head inverse norm (per 8-lane group = one factor) ----
    float ss = acc.x * acc.x + acc.y * acc.y;
    #pragma unroll
    for (int o = 4; o >= 1; o >>= 1) ss += __shfl_xor_sync(0xffffffffu, ss, o);
    const float hinv = 1.0f / fmaxf(sqrtf(ss), 1e-12f);
    sm_h[warp][lane] = make_float2(acc.x * hinv, acc.y * hinv);
    __syncwarp();

    // ---- routing: lane-per-edge, per-lane softmax, fp16 Tn row ----
    const float4* hp4 = reinterpret_cast<const float4*>(&sm_h[warp][0]);
    float4 dval = make_float4(0.f, 0.f, 0.f, 0.f);
    for (int base = s; base < e; base += 32) {
        int j = base + lane;
        if (j < e) {
            int t = g_csr_t[j];
            const uint4* tn = &g_TnV[t * 8];
            float q0 = 0.f, q1 = 0.f, q2 = 0.f, q3 = 0.f;
            #pragma unroll
            for (int c = 0; c < 8; c++) {
                uint4 v = tn[c];                         // dims [8c, 8c+7], factor c>>1
                float2 ta = __half22float2(*reinterpret_cast<__half2*>(&v.x));
                float2 tb = __half22float2(*reinterpret_cast<__half2*>(&v.y));
                float2 tc = __half22float2(*reinterpret_cast<__half2*>(&v.z));
                float2 td = __half22float2(*reinterpret_cast<__half2*>(&v.w));
                float4 h0 = hp4[2 * c];
                float4 h1 = hp4[2 * c + 1];
                float qq = h0.x*ta.x + h0.y*ta.y + h0.z*tb.x + h0.w*tb.y
                         + h1.x*tc.x + h1.y*tc.y + h1.z*td.x + h1.w*td.y;
                if ((c >> 1) == 0) q0 += qq;
                else if ((c >> 1) == 1) q1 += qq;
                else if ((c >> 1) == 2) q2 += qq;
                else q3 += qq;
            }
            float4 An = Ap[j];
            An.x += q0; An.y += q1; An.z += q2; An.w += q3;
            float m  = fmaxf(fmaxf(An.x, An.y), fmaxf(An.z, An.w));
            float e0 = __expf(An.x - m), e1 = __expf(An.y - m);
            float e2 = __expf(An.z - m), e3 = __expf(An.w - m);
            float inv = 1.0f / (e0 + e1 + e2 + e3);
            Ap[j] = An;
            float4 nA = make_float4(e0 * inv, e1 * inv, e2 * inv, e3 * inv);
            normAo[j] = nA;
            dval.x += nA.x; dval.y += nA.y; dval.z += nA.z; dval.w += nA.w;
        }
    }
    // reduce dval across warp -> next iteration's dinv for this node
    #pragma unroll
    for (int o = 16; o >= 1; o >>= 1) {
        dval.x += __shfl_xor_sync(0xffffffffu, dval.x, o);
        dval.y += __shfl_xor_sync(0xffffffffu, dval.y, o);
        dval.z += __shfl_xor_sync(0xffffffffu, dval.z, o);
        dval.w += __shfl_xor_sync(0xffffffffu, dval.w, o);
    }
    if (lane == 0) {
        dinvN[w] = make_float4(rsqrtf(fmaxf(dval.x, 1e-8f)),
                               rsqrtf(fmaxf(dval.y, 1e-8f)),
                               rsqrtf(fmaxf(dval.z, 1e-8f)),
                               rsqrtf(fmaxf(dval.w, 1e-8f)));
    }
}

// ---------------- host driver ----------------
extern "C" void kernel_launch(void* const* d_in, const int* in_sizes, int n_in,
                              void* d_out, int out_size) {
    const float* user = (const float*)d_in[0];
    const float* item = (const float*)d_in[1];
    const int*   hl   = (const int*)d_in[2];
    const int*   tl   = (const int*)d_in[3];
    float* out = (float*)d_out;

    const int TB = 256;
    k_init_ego<<<(kN * kD + TB - 1) / TB, TB>>>(user, item);
    k_zero_cnt<<<(kN + TB - 1) / TB, TB>>>();
    k_count<<<(kE + TB - 1) / TB, TB>>>(hl);
    k_chunk_reduce<<<kNChunk, TB>>>();
    k_bsum_scan<<<1, 32>>>();
    k_chunk_scan<<<kNChunk, TB>>>();
    k_fill<<<(kE + TB - 1) / TB, TB>>>(hl, tl);
    k_dinv0<<<(kN + TB - 1) / TB, TB>>>();

    const int FG = kN / 8;   // 8 warps / block
    const int RG = (kN * 4 + TB - 1) / TB;
    // layer 0: ego=buf0 -> fe=buf1
    k_tail<<<RG, TB>>>(0);                      // Tn(buf0) fp16, egoS = buf0*dinvA(init)
    k_fused<<<FG, TB>>>(0, 0, 0, out);          // it0: reads dinvA, writes dinvB; no fe
    k_rescale<<<RG, TB>>>(0);                   // egoS = buf0*dinvB
    k_fused<<<FG, TB>>>(0, 1, 1, out);          // it1: reads dinvB, writes dinvA; fe->buf1
    // layer 1: ego=buf1 -> out
    k_tail<<<RG, TB>>>(1);                      // Tn(buf1) fp16, egoS = buf1*dinvA
    k_fused<<<FG, TB>>>(1, 0, 0, out);          // it0: reads dinvA, writes dinvB; no fe
    k_rescale<<<RG, TB>>>(1);                   // egoS = buf1*dinvB
    k_fused<<<FG, TB>>>(1, 1, 2, out);          // final: reads dinvB, no routing
    (void)in_sizes; (void)n_in; (void)out_size;
}

// round 11
// speedup vs baseline: 1.5100x; 1.0999x over previous
#include <cuda_runtime.h>
#include <cuda_fp16.h>
#include <cuda_bf16.h>

namespace {
constexpr int kNUser = 50000;
constexpr int kN     = 80000;      // total nodes
constexpr int kE     = 1000000;    // 2 * NNZ symmetric edges
constexpr int kD     = 64;
constexpr int kChunk = 1024;
constexpr int kNChunk = (kN + kChunk - 1) / kChunk;   // 79
}

// ---------------- device scratch (static, no allocation) ----------------
__device__ float g_A[kE * 4];         // routing logits, CSR-slot order
__device__ float g_normA[kE * 4];     // softmax(A), CSR-slot order
__device__ float g_buf0[kN * kD];     // initial ego (layer-0 input; never overwritten)
__device__ float g_buf1[kN * kD];     // layer-0 output = layer-1 input
__device__ __half2 g_egoS[kN * 32];   // layer ego prescaled by current dinv (fp16, 128B/node)
__device__ uint4 g_TnV[kN * 8];       // tanh(normalized tail chunks), fp16, 128B/node
__device__ float g_dinvA[kN * 4];     // 1/sqrt(degree-weight), ping
__device__ float g_dinvB[kN * 4];     // pong
__device__ int   g_ptr[kN + 1];       // CSR row pointers (by head)
__device__ int   g_cnt[kN];           // histogram / fill counters
__device__ int   g_csr_t[kE];         // tail node per CSR slot
__device__ int   g_bsum[kNChunk];     // per-chunk sums for multi-block scan

__device__ __forceinline__ unsigned pack_h2(float a, float b) {
    __half2 h = __floats2half2_rn(a, b);
    return *reinterpret_cast<unsigned*>(&h);
}

// ---------------- init (+ cnt zeroing folded in) ----------------
__global__ void k_init_ego(const float* __restrict__ user, const float* __restrict__ item) {
    int i = blockIdx.x * blockDim.x + threadIdx.x;
    if (i >= kN * kD) return;
    g_buf0[i] = (i < kNUser * kD) ? user[i] : item[i - kNUser * kD];
    if (i < kN) g_cnt[i] = 0;
}

// ---------------- CSR build ----------------
__global__ void k_count(const int* __restrict__ h) {
    int e = blockIdx.x * blockDim.x + threadIdx.x;
    if (e >= kE) return;
    atomicAdd(&g_cnt[h[e]], 1);
}

__global__ void k_chunk_reduce() {            // kNChunk blocks x 256
    __shared__ int wsum[8];
    const int lane = threadIdx.x & 31, wrp = threadIdx.x >> 5;
    int base = blockIdx.x * kChunk + (int)threadIdx.x * 4;
    int s = 0;
    #pragma unroll
    for (int k = 0; k < 4; k++) { int i = base + k; if (i < kN) s += g_cnt[i]; }
    #pragma unroll
    for (int o = 16; o >= 1; o >>= 1) s += __shfl_xor_sync(0xffffffffu, s, o);
    if (lane == 0) wsum[wrp] = s;
    __syncthreads();
    if (threadIdx.x == 0) {
        int t = 0;
        #pragma unroll
        for (int k = 0; k < 8; k++) t += wsum[k];
        g_bsum[blockIdx.x] = t;
    }
}

__global__ void k_bsum_scan() {               // 1 block x 32
    const int lane = threadIdx.x;
    int carry = 0;
    for (int base = 0; base < kNChunk; base += 32) {
        int i = base + lane;
        int v = (i < kNChunk) ? g_bsum[i] : 0;
        int x = v;
        #pragma unroll
        for (int o = 1; o < 32; o <<= 1) {
            int y = __shfl_up_sync(0xffffffffu, x, o);
            if (lane >= o) x += y;
        }
        if (i < kNChunk) g_bsum[i] = carry + x - v;     // exclusive
        carry += __shfl_sync(0xffffffffu, x, 31);
    }
    if (lane == 0) g_ptr[kN] = carry;
}

// chunk scan + dinv0 folded in (degree is in registers here)
__global__ void k_chunk_scan() {              // kNChunk blocks x 256
    __shared__ int wsum[8];
    const int lane = threadIdx.x & 31, wrp = threadIdx.x >> 5;
    int base = blockIdx.x * kChunk + (int)threadIdx.x * 4;
    int v0 = 0, v1 = 0, v2 = 0, v3 = 0;
    if (base + 3 < kN) {
        int4 v = *reinterpret_cast<const int4*>(&g_cnt[base]);
        v0 = v.x; v1 = v.y; v2 = v.z; v3 = v.w;
    } else {
        if (base + 0 < kN) v0 = g_cnt[base + 0];
        if (base + 1 < kN) v1 = g_cnt[base + 1];
        if (base + 2 < kN) v2 = g_cnt[base + 2];
        if (base + 3 < kN) v3 = g_cnt[base + 3];
    }
    int tot = v0 + v1 + v2 + v3;
    int x = tot;
    #pragma unroll
    for (int o = 1; o < 32; o <<= 1) {
        int y = __shfl_up_sync(0xffffffffu, x, o);
        if (lane >= o) x += y;
    }
    if (lane == 31) wsum[wrp] = x;
    __syncthreads();
    if (wrp == 0 && lane < 8) {
        int s = wsum[lane], xs = s;
        #pragma unroll
        for (int o = 1; o < 8; o <<= 1) {
            int y = __shfl_up_sync(0xffu, xs, o);
            if (lane >= o) xs += y;
        }
        wsum[lane] = xs - s;
    }
    __syncthreads();
    int ex = g_bsum[blockIdx.x] + wsum[wrp] + (x - tot);
    int vv[4] = {v0, v1, v2, v3};
    int pre[4] = {0, v0, v0 + v1, v0 + v1 + v2};
    #pragma unroll
    for (int k = 0; k < 4; k++) {
        int n = base + k;
        if (n < kN) {
            g_ptr[n] = ex + pre[k];
            g_cnt[n] = 0;
            float di = rsqrtf(fmaxf(0.25f * (float)vv[k], 1e-8f));
            reinterpret_cast<float4*>(g_dinvA)[n] = make_float4(di, di, di, di);
        }
    }
}

// fill CSR + initialize A=1, normA=0.25 in slot order
__global__ void k_fill(const int* __restrict__ h, const int* __restrict__ t) {
    int e = blockIdx.x * blockDim.x + threadIdx.x;
    if (e >= kE) return;
    int hn   = h[e];
    int slot = g_ptr[hn] + atomicAdd(&g_cnt[hn], 1);
    g_csr_t[slot] = t[e];
    reinterpret_cast<float4*>(g_A)[slot]     = make_float4(1.f, 1.f, 1.f, 1.f);
    reinterpret_cast<float4*>(g_normA)[slot] = make_float4(.25f, .25f, .25f, .25f);
}

// ---------------- per-layer: tanh(normalized tail chunks)->fp16 + egoS(fp16) = ego*dinvA ----------------
__global__ void k_tail(int sel) {
    const float* ego = sel ? g_buf1 : g_buf0;
    int i = blockIdx.x * blockDim.x + threadIdx.x;   // (node, factor)
    if (i >= kN * 4) return;
    const float4* src = reinterpret_cast<const float4*>(ego) + i * 4;
    float4 v0 = src[0], v1 = src[1], v2 = src[2], v3 = src[3];
    float ss = v0.x*v0.x + v0.y*v0.y + v0.z*v0.z + v0.w*v0.w
             + v1.x*v1.x + v1.y*v1.y + v1.z*v1.z + v1.w*v1.w
             + v2.x*v2.x + v2.y*v2.y + v2.z*v2.z + v2.w*v2.w
             + v3.x*v3.x + v3.y*v3.y + v3.z*v3.z + v3.w*v3.w;
    float inv = 1.0f / fmaxf(sqrtf(ss), 1e-12f);
    uint4 u0, u1;
    u0.x = pack_h2(tanhf(v0.x*inv), tanhf(v0.y*inv));
    u0.y = pack_h2(tanhf(v0.z*inv), tanhf(v0.w*inv));
    u0.z = pack_h2(tanhf(v1.x*inv), tanhf(v1.y*inv));
    u0.w = pack_h2(tanhf(v1.z*inv), tanhf(v1.w*inv));
    u1.x = pack_h2(tanhf(v2.x*inv), tanhf(v2.y*inv));
    u1.y = pack_h2(tanhf(v2.z*inv), tanhf(v2.w*inv));
    u1.z = pack_h2(tanhf(v3.x*inv), tanhf(v3.y*inv));
    u1.w = pack_h2(tanhf(v3.z*inv), tanhf(v3.w*inv));
    g_TnV[i * 2]     = u0;
    g_TnV[i * 2 + 1] = u1;
    float di = g_dinvA[i];
    uint4 s0, s1;
    s0.x = pack_h2(v0.x*di, v0.y*di);
    s0.y = pack_h2(v0.z*di, v0.w*di);
    s0.z = pack_h2(v1.x*di, v1.y*di);
    s0.w = pack_h2(v1.z*di, v1.w*di);
    s1.x = pack_h2(v2.x*di, v2.y*di);
    s1.y = pack_h2(v2.z*di, v2.w*di);
    s1.z = pack_h2(v3.x*di, v3.y*di);
    s1.w = pack_h2(v3.z*di, v3.w*di);
    reinterpret_cast<uint4*>(g_egoS)[i * 2]     = s0;
    reinterpret_cast<uint4*>(g_egoS)[i * 2 + 1] = s1;
}

// ---------------- between iterations: egoS(fp16) = ego * dinvB (coalesced) ----------------
__global__ void k_rescale(int sel) {
    const float* ego = sel ? g_buf1 : g_buf0;
    int i = blockIdx.x * blockDim.x + threadIdx.x;   // (node, factor)
    if (i >= kN * 4) return;
    const float4* src = reinterpret_cast<const float4*>(ego) + i * 4;
    float di = g_dinvB[i];
    float4 v0 = src[0], v1 = src[1], v2 = src[2], v3 = src[3];
    uint4 s0, s1;
    s0.x = pack_h2(v0.x*di, v0.y*di);
    s0.y = pack_h2(v0.z*di, v0.w*di);
    s0.z = pack_h2(v1.x*di, v1.y*di);
    s0.w = pack_h2(v1.z*di, v1.w*di);
    s1.x = pack_h2(v2.x*di, v2.y*di);
    s1.y = pack_h2(v2.z*di, v2.w*di);
    s1.z = pack_h2(v3.x*di, v3.y*di);
    s1.w = pack_h2(v3.z*di, v3.w*di);
    reinterpret_cast<uint4*>(g_egoS)[i * 2]     = s0;
    reinterpret_cast<uint4*>(g_egoS)[i * 2 + 1] = s1;
}

// ---------------- fused iteration ----------------
// one warp per node. MP: lane owns dims [2l,2l+1] (one __half2), factor f = lane>>3,
// smem-staged edge weights; egoS row = 128B fp16 -> 1 L1tex line per edge.
// Routing: lane-per-edge, per-lane softmax (R10 structure, unchanged).
// mode: 0 = routing, fe NOT written; 1 = routing + fe write; 2 = final output.
__global__ void __launch_bounds__(256) k_fused(
        int sel_in, int dsel, int mode, float* __restrict__ out)
{
    __shared__ int    sm_t[8][32];
    __shared__ float  sm_wT[8][4][33];
    __shared__ float2 sm_h[8][32];      // normalized head (64 floats / warp)

    const int warp = threadIdx.x >> 5;
    const int lane = threadIdx.x & 31;
    const int w = blockIdx.x * 8 + warp;
    const int f = lane >> 3;

    const float*  ego    = sel_in ? g_buf1 : g_buf0;
    float*        fe     = sel_in ? g_buf0 : g_buf1;   // only written in mode 1 (sel_in=0)
    const float4* dinvC  = reinterpret_cast<const float4*>(dsel ? g_dinvB : g_dinvA);
    float4*       dinvN  = reinterpret_cast<float4*>(dsel ? g_dinvA : g_dinvB);
    const float4* normA  = reinterpret_cast<const float4*>(g_normA);
    float4*       normAo = reinterpret_cast<float4*>(g_normA);
    float4*       Ap     = reinterpret_cast<float4*>(g_A);

    const int s = g_ptr[w], e = g_ptr[w + 1];

    // ---- message passing ----
    float2 acc = make_float2(0.f, 0.f);
    for (int base = s; base < e; base += 32) {
        int j = base + lane;
        bool valid = j < e;
        int t = valid ? g_csr_t[j] : 0;
        float4 na = valid ? normA[j] : make_float4(0.f, 0.f, 0.f, 0.f);
        sm_t[warp][lane] = t;
        sm_wT[warp][0][lane] = na.x;
        sm_wT[warp][1][lane] = na.y;
        sm_wT[warp][2][lane] = na.z;
        sm_wT[warp][3][lane] = na.w;
        __syncwarp();
        int cnt = min(32, e - base);
        #pragma unroll 8
        for (int k = 0; k < cnt; k++) {
            int   tk = sm_t[warp][k];
            float wk = sm_wT[warp][f][k];
            float2 ev = __half22float2(g_egoS[tk * 32 + lane]);
            acc.x += wk * ev.x;
            acc.y += wk * ev.y;
        }
        __syncwarp();
    }
    {
        float4 dh = dinvC[w];
        float ds = (f == 0) ? dh.x : (f == 1) ? dh.y : (f == 2) ? dh.z : dh.w;
        acc.x *= ds; acc.y *= ds;
    }

    if (mode == 2) {
        // final: out = (initial_ego(buf0) + layer1_input(buf1) + fe)/3
        float2 a = reinterpret_cast<const float2*>(g_buf0 + w * kD)[lane];
        float2 b = reinterpret_cast<const float2*>(ego + w * kD)[lane];
        float2 o;
        o.x = (a.x + b.x + acc.x) * (1.0f / 3.0f);
        o.y = (a.y + b.y + acc.y) * (1.0f / 3.0f);
        reinterpret_cast<float2*>(out + w * kD)[lane] = o;
        return;
    }

    if (mode == 1)
        reinterpret_cast<float2*>(fe + w * kD)[lane] = acc;

    // ---- head inverse norm (per 8-lane group = one factor) ----
    float ss = acc.x * acc.x + acc.y * acc.y;
    #pragma unroll
    for (int o = 4; o >= 1; o >>= 1) ss += __shfl_xor_sync(0xffffffffu, ss, o);
    const float hinv = 1.0f / fmaxf(sqrtf(ss), 1e-12f);
    sm_h[warp][lane] = make_float2(acc.x * hinv, acc.y * hinv);
    __syncwarp();

    // ---- routing: lane-per-edge, per-lane softmax, fp16 Tn row ----
    const float4* hp4 = reinterpret_cast<const float4*>(&sm_h[warp][0]);
    float4 dval = make_float4(0.f, 0.f, 0.f, 0.f);
    for (int base = s; base < e; base += 32) {
        int j = base + lane;
        if (j < e) {
            int t = g_csr_t[j];
            const uint4* tn = &g_TnV[t * 8];
            float q0 = 0.f, q1 = 0.f, q2 = 0.f, q3 = 0.f;
            #pragma unroll
            for (int c = 0; c < 8; c++) {
                uint4 v = tn[c];                         // dims [8c, 8c+7], factor c>>1
                float2 ta = __half22float2(*reinterpret_cast<__half2*>(&v.x));
                float2 tb = __half22float2(*reinterpret_cast<__half2*>(&v.y));
                float2 tc = __half22float2(*reinterpret_cast<__half2*>(&v.z));
                float2 td = __half22float2(*reinterpret_cast<__half2*>(&v.w));
                float4 h0 = hp4[2 * c];
                float4 h1 = hp4[2 * c + 1];
                float qq = h0.x*ta.x + h0.y*ta.y + h0.z*tb.x + h0.w*tb.y
                         + h1.x*tc.x + h1.y*tc.y + h1.z*td.x + h1.w*td.y;
                if ((c >> 1) == 0) q0 += qq;
                else if ((c >> 1) == 1) q1 += qq;
                else if ((c >> 1) == 2) q2 += qq;
                else q3 += qq;
            }
            float4 An = Ap[j];
            An.x += q0; An.y += q1; An.z += q2; An.w += q3;
            float m  = fmaxf(fmaxf(An.x, An.y), fmaxf(An.z, An.w));
            float e0 = __expf(An.x - m), e1 = __expf(An.y - m);
            float e2 = __expf(An.z - m), e3 = __expf(An.w - m);
            float inv = 1.0f / (e0 + e1 + e2 + e3);
            Ap[j] = An;
            float4 nA = make_float4(e0 * inv, e1 * inv, e2 * inv, e3 * inv);
            normAo[j] = nA;
            dval.x += nA.x; dval.y += nA.y; dval.z += nA.z; dval.w += nA.w;
        }
    }
    // reduce dval across warp -> next iteration's dinv for this node
    #pragma unroll
    for (int o = 16; o >= 1; o >>= 1) {
        dval.x += __shfl_xor_sync(0xffffffffu, dval.x, o);
        dval.y += __shfl_xor_sync(0xffffffffu, dval.y, o);
        dval.z += __shfl_xor_sync(0xffffffffu, dval.z, o);
        dval.w += __shfl_xor_sync(0xffffffffu, dval.w, o);
    }
    if (lane == 0) {
        dinvN[w] = make_float4(rsqrtf(fmaxf(dval.x, 1e-8f)),
                               rsqrtf(fmaxf(dval.y, 1e-8f)),
                               rsqrtf(fmaxf(dval.z, 1e-8f)),
                               rsqrtf(fmaxf(dval.w, 1e-8f)));
    }
}

// ---------------- host driver ----------------
extern "C" void kernel_launch(void* const* d_in, const int* in_sizes, int n_in,
                              void* d_out, int out_size) {
    const float* user = (const float*)d_in[0];
    const float* item = (const float*)d_in[1];
    const int*   hl   = (const int*)d_in[2];
    const int*   tl   = (const int*)d_in[3];
    float* out = (float*)d_out;

    const int TB = 256;
    k_init_ego<<<(kN * kD + TB - 1) / TB, TB>>>(user, item);   // + cnt zeroing
    k_count<<<(kE + TB - 1) / TB, TB>>>(hl);
    k_chunk_reduce<<<kNChunk, TB>>>();
    k_bsum_scan<<<1, 32>>>();
    k_chunk_scan<<<kNChunk, TB>>>();                           // + dinv0
    k_fill<<<(kE + TB - 1) / TB, TB>>>(hl, tl);

    const int FG = kN / 8;   // 8 warps / block
    const int RG = (kN * 4 + TB - 1) / TB;
    // layer 0: ego=buf0 -> fe=buf1
    k_tail<<<RG, TB>>>(0);                      // Tn(buf0) fp16, egoS = buf0*dinvA(init)
    k_fused<<<FG, TB>>>(0, 0, 0, out);          // it0: reads dinvA, writes dinvB; no fe
    k_rescale<<<RG, TB>>>(0);                   // egoS = buf0*dinvB
    k_fused<<<FG, TB>>>(0, 1, 1, out);          // it1: reads dinvB, writes dinvA; fe->buf1
    // layer 1: ego=buf1 -> out
    k_tail<<<RG, TB>>>(1);                      // Tn(buf1) fp16, egoS = buf1*dinvA
    k_fused<<<FG, TB>>>(1, 0, 0, out);          // it0: reads dinvA, writes dinvB; no fe
    k_rescale<<<RG, TB>>>(1);                   // egoS = buf1*dinvB
    k_fused<<<FG, TB>>>(1, 1, 2, out);          // final: reads dinvB, no routing
    (void)in_sizes; (void)n_in; (void)out_size;
}

// round 12
// speedup vs baseline: 1.5333x; 1.0154x over previous
#include <cuda_runtime.h>
#include <cuda_fp16.h>
#include <cuda_bf16.h>

namespace {
constexpr int kNUser = 50000;
constexpr int kN     = 80000;      // total nodes
constexpr int kE     = 1000000;    // 2 * NNZ symmetric edges
constexpr int kD     = 64;
constexpr int kChunk = 1024;
constexpr int kNChunk = (kN + kChunk - 1) / kChunk;   // 79
}

// ---------------- device scratch (static, no allocation) ----------------
__device__ float    g_A[kE * 4];        // routing logits, CSR-slot order
__device__ float    g_normA[kE * 4];    // softmax(A), CSR-slot order
__device__ float    g_buf0[kN * kD];    // initial ego (layer-0 input; never overwritten)
__device__ float    g_buf1[kN * kD];    // layer-0 output = layer-1 input
__device__ unsigned g_egoS0[kN * 32];   // prescaled ego, fp16 x2, ping (128B/node)
__device__ unsigned g_egoS1[kN * 32];   // pong
__device__ unsigned g_Tn0[kN * 32];     // tanh(normalized chunks), fp16 x2, ping
__device__ unsigned g_Tn1[kN * 32];     // pong
__device__ float    g_dinvA[kN * 4];    // 1/sqrt(degree-weight), ping
__device__ float    g_dinvB[kN * 4];    // pong
__device__ int      g_ptr[kN + 1];      // CSR row pointers (by head)
__device__ int      g_cnt[kN];          // histogram / fill counters
__device__ int      g_csr_t[kE];        // tail node per CSR slot
__device__ int      g_bsum[kNChunk];    // per-chunk sums for multi-block scan

__device__ __forceinline__ unsigned pack_h2(float a, float b) {
    __half2 h = __floats2half2_rn(a, b);
    return *reinterpret_cast<unsigned*>(&h);
}

// ---------------- init (+ cnt zeroing folded in) ----------------
__global__ void k_init_ego(const float* __restrict__ user, const float* __restrict__ item) {
    int i = blockIdx.x * blockDim.x + threadIdx.x;
    if (i >= kN * kD) return;
    g_buf0[i] = (i < kNUser * kD) ? user[i] : item[i - kNUser * kD];
    if (i < kN) g_cnt[i] = 0;
}

// ---------------- CSR build ----------------
__global__ void k_count(const int* __restrict__ h) {
    int e = blockIdx.x * blockDim.x + threadIdx.x;
    if (e >= kE) return;
    atomicAdd(&g_cnt[h[e]], 1);
}

__global__ void k_chunk_reduce() {            // kNChunk blocks x 256
    __shared__ int wsum[8];
    const int lane = threadIdx.x & 31, wrp = threadIdx.x >> 5;
    int base = blockIdx.x * kChunk + (int)threadIdx.x * 4;
    int s = 0;
    #pragma unroll
    for (int k = 0; k < 4; k++) { int i = base + k; if (i < kN) s += g_cnt[i]; }
    #pragma unroll
    for (int o = 16; o >= 1; o >>= 1) s += __shfl_xor_sync(0xffffffffu, s, o);
    if (lane == 0) wsum[wrp] = s;
    __syncthreads();
    if (threadIdx.x == 0) {
        int t = 0;
        #pragma unroll
        for (int k = 0; k < 8; k++) t += wsum[k];
        g_bsum[blockIdx.x] = t;
    }
}

__global__ void k_bsum_scan() {               // 1 block x 32
    const int lane = threadIdx.x;
    int carry = 0;
    for (int base = 0; base < kNChunk; base += 32) {
        int i = base + lane;
        int v = (i < kNChunk) ? g_bsum[i] : 0;
        int x = v;
        #pragma unroll
        for (int o = 1; o < 32; o <<= 1) {
            int y = __shfl_up_sync(0xffffffffu, x, o);
            if (lane >= o) x += y;
        }
        if (i < kNChunk) g_bsum[i] = carry + x - v;     // exclusive
        carry += __shfl_sync(0xffffffffu, x, 31);
    }
    if (lane == 0) g_ptr[kN] = carry;
}

// chunk scan + dinv0 folded in (degree is in registers here)
__global__ void k_chunk_scan() {              // kNChunk blocks x 256
    __shared__ int wsum[8];
    const int lane = threadIdx.x & 31, wrp = threadIdx.x >> 5;
    int base = blockIdx.x * kChunk + (int)threadIdx.x * 4;
    int v0 = 0, v1 = 0, v2 = 0, v3 = 0;
    if (base + 3 < kN) {
        int4 v = *reinterpret_cast<const int4*>(&g_cnt[base]);
        v0 = v.x; v1 = v.y; v2 = v.z; v3 = v.w;
    } else {
        if (base + 0 < kN) v0 = g_cnt[base + 0];
        if (base + 1 < kN) v1 = g_cnt[base + 1];
        if (base + 2 < kN) v2 = g_cnt[base + 2];
        if (base + 3 < kN) v3 = g_cnt[base + 3];
    }
    int tot = v0 + v1 + v2 + v3;
    int x = tot;
    #pragma unroll
    for (int o = 1; o < 32; o <<= 1) {
        int y = __shfl_up_sync(0xffffffffu, x, o);
        if (lane >= o) x += y;
    }
    if (lane == 31) wsum[wrp] = x;
    __syncthreads();
    if (wrp == 0 && lane < 8) {
        int s = wsum[lane], xs = s;
        #pragma unroll
        for (int o = 1; o < 8; o <<= 1) {
            int y = __shfl_up_sync(0xffu, xs, o);
            if (lane >= o) xs += y;
        }
        wsum[lane] = xs - s;
    }
    __syncthreads();
    int ex = g_bsum[blockIdx.x] + wsum[wrp] + (x - tot);
    int vv[4] = {v0, v1, v2, v3};
    int pre[4] = {0, v0, v0 + v1, v0 + v1 + v2};
    #pragma unroll
    for (int k = 0; k < 4; k++) {
        int n = base + k;
        if (n < kN) {
            g_ptr[n] = ex + pre[k];
            g_cnt[n] = 0;
            float di = rsqrtf(fmaxf(0.25f * (float)vv[k], 1e-8f));
            reinterpret_cast<float4*>(g_dinvA)[n] = make_float4(di, di, di, di);
        }
    }
}

// fill CSR + initialize A=1, normA=0.25 in slot order
__global__ void k_fill(const int* __restrict__ h, const int* __restrict__ t) {
    int e = blockIdx.x * blockDim.x + threadIdx.x;
    if (e >= kE) return;
    int hn   = h[e];
    int slot = g_ptr[hn] + atomicAdd(&g_cnt[hn], 1);
    g_csr_t[slot] = t[e];
    reinterpret_cast<float4*>(g_A)[slot]     = make_float4(1.f, 1.f, 1.f, 1.f);
    reinterpret_cast<float4*>(g_normA)[slot] = make_float4(.25f, .25f, .25f, .25f);
}

// ---------------- layer-0 prep: Tn0 = tanh(norm(buf0)), egoS0 = buf0*dinvA ----------------
__global__ void k_tail0() {
    int i = blockIdx.x * blockDim.x + threadIdx.x;   // (node, factor)
    if (i >= kN * 4) return;
    const float4* src = reinterpret_cast<const float4*>(g_buf0) + i * 4;
    float4 v0 = src[0], v1 = src[1], v2 = src[2], v3 = src[3];
    float ss = v0.x*v0.x + v0.y*v0.y + v0.z*v0.z + v0.w*v0.w
             + v1.x*v1.x + v1.y*v1.y + v1.z*v1.z + v1.w*v1.w
             + v2.x*v2.x + v2.y*v2.y + v2.z*v2.z + v2.w*v2.w
             + v3.x*v3.x + v3.y*v3.y + v3.z*v3.z + v3.w*v3.w;
    float inv = 1.0f / fmaxf(sqrtf(ss), 1e-12f);
    uint4 u0, u1;
    u0.x = pack_h2(tanhf(v0.x*inv), tanhf(v0.y*inv));
    u0.y = pack_h2(tanhf(v0.z*inv), tanhf(v0.w*inv));
    u0.z = pack_h2(tanhf(v1.x*inv), tanhf(v1.y*inv));
    u0.w = pack_h2(tanhf(v1.z*inv), tanhf(v1.w*inv));
    u1.x = pack_h2(tanhf(v2.x*inv), tanhf(v2.y*inv));
    u1.y = pack_h2(tanhf(v2.z*inv), tanhf(v2.w*inv));
    u1.z = pack_h2(tanhf(v3.x*inv), tanhf(v3.y*inv));
    u1.w = pack_h2(tanhf(v3.z*inv), tanhf(v3.w*inv));
    reinterpret_cast<uint4*>(g_Tn0)[i * 2]     = u0;
    reinterpret_cast<uint4*>(g_Tn0)[i * 2 + 1] = u1;
    float di = g_dinvA[i];
    uint4 s0, s1;
    s0.x = pack_h2(v0.x*di, v0.y*di);
    s0.y = pack_h2(v0.z*di, v0.w*di);
    s0.z = pack_h2(v1.x*di, v1.y*di);
    s0.w = pack_h2(v1.z*di, v1.w*di);
    s1.x = pack_h2(v2.x*di, v2.y*di);
    s1.y = pack_h2(v2.z*di, v2.w*di);
    s1.z = pack_h2(v3.x*di, v3.y*di);
    s1.w = pack_h2(v3.z*di, v3.w*di);
    reinterpret_cast<uint4*>(g_egoS0)[i * 2]     = s0;
    reinterpret_cast<uint4*>(g_egoS0)[i * 2 + 1] = s1;
}

// ---------------- fused iteration ----------------
// one warp per node. MP: lane owns dims [2l,2l+1] (one __half2), factor f = lane>>3,
// smem-staged edge weights; egoS row = 128B fp16 -> 1 line per edge.
// Routing: lane-per-edge, per-lane softmax.
// Epilogue writes next-iteration egoS (and, in mode 1, next-layer Tn) to the
// OTHER buffer -- race-free double buffering, replaces k_rescale/k_tail.
// mode: 0 = routing, egoS_next = ego[w]*dinvN
//       1 = routing + fe write, egoS_next = acc*dinvN, Tn_next = tanh(acc*hinv)
//       2 = final output
__global__ void __launch_bounds__(256) k_fused(
        int sel_in, int dsel, int esel, int tsel, int mode, float* __restrict__ out)
{
    __shared__ int    sm_t[8][32];
    __shared__ float  sm_wT[8][4][33];
    __shared__ float2 sm_h[8][32];      // normalized head (64 floats / warp)

    const int warp = threadIdx.x >> 5;
    const int lane = threadIdx.x & 31;
    const int w = blockIdx.x * 8 + warp;
    const int f = lane >> 3;

    const float*    ego    = sel_in ? g_buf1 : g_buf0;
    float*          fe     = sel_in ? g_buf0 : g_buf1;   // only written in mode 1 (sel_in=0)
    const unsigned* egoSC  = esel ? g_egoS1 : g_egoS0;
    unsigned*       egoSN  = esel ? g_egoS0 : g_egoS1;
    const unsigned* TnC    = tsel ? g_Tn1 : g_Tn0;
    unsigned*       TnN    = tsel ? g_Tn0 : g_Tn1;
    const float4*   dinvC  = reinterpret_cast<const float4*>(dsel ? g_dinvB : g_dinvA);
    float4*         dinvN  = reinterpret_cast<float4*>(dsel ? g_dinvA : g_dinvB);
    const float4*   normA  = reinterpret_cast<const float4*>(g_normA);
    float4*         normAo = reinterpret_cast<float4*>(g_normA);
    float4*         Ap     = reinterpret_cast<float4*>(g_A);

    const int s = g_ptr[w], e = g_ptr[w + 1];

    // ---- message passing ----
    float2 acc = make_float2(0.f, 0.f);
    for (int base = s; base < e; base += 32) {
        int j = base + lane;
        bool valid = j < e;
        int t = valid ? g_csr_t[j] : 0;
        float4 na = valid ? normA[j] : make_float4(0.f, 0.f, 0.f, 0.f);
        sm_t[warp][lane] = t;
        sm_wT[warp][0][lane] = na.x;
        sm_wT[warp][1][lane] = na.y;
        sm_wT[warp][2][lane] = na.z;
        sm_wT[warp][3][lane] = na.w;
        __syncwarp();
        int cnt = min(32, e - base);
        #pragma unroll 8
        for (int k = 0; k < cnt; k++) {
            int   tk = sm_t[warp][k];
            float wk = sm_wT[warp][f][k];
            float2 ev = __half22float2(*reinterpret_cast<const __half2*>(&egoSC[tk * 32 + lane]));
            acc.x += wk * ev.x;
            acc.y += wk * ev.y;
        }
        __syncwarp();
    }
    {
        float4 dh = dinvC[w];
        float ds = (f == 0) ? dh.x : (f == 1) ? dh.y : (f == 2) ? dh.z : dh.w;
        acc.x *= ds; acc.y *= ds;
    }

    if (mode == 2) {
        // final: out = (initial_ego(buf0) + layer1_input(buf1) + fe)/3
        float2 a = reinterpret_cast<const float2*>(g_buf0 + w * kD)[lane];
        float2 b = reinterpret_cast<const float2*>(ego + w * kD)[lane];
        float2 o;
        o.x = (a.x + b.x + acc.x) * (1.0f / 3.0f);
        o.y = (a.y + b.y + acc.y) * (1.0f / 3.0f);
        reinterpret_cast<float2*>(out + w * kD)[lane] = o;
        return;
    }

    if (mode == 1)
        reinterpret_cast<float2*>(fe + w * kD)[lane] = acc;

    // ---- head inverse norm (per 8-lane group = one factor) ----
    float ss = acc.x * acc.x + acc.y * acc.y;
    #pragma unroll
    for (int o = 4; o >= 1; o >>= 1) ss += __shfl_xor_sync(0xffffffffu, ss, o);
    const float hinv = 1.0f / fmaxf(sqrtf(ss), 1e-12f);
    sm_h[warp][lane] = make_float2(acc.x * hinv, acc.y * hinv);
    __syncwarp();

    // ---- routing: lane-per-edge, per-lane softmax, fp16 Tn row ----
    const float4* hp4 = reinterpret_cast<const float4*>(&sm_h[warp][0]);
    float4 dval = make_float4(0.f, 0.f, 0.f, 0.f);
    for (int base = s; base < e; base += 32) {
        int j = base + lane;
        if (j < e) {
            int t = g_csr_t[j];
            const uint4* tn = reinterpret_cast<const uint4*>(TnC) + t * 8;
            float q0 = 0.f, q1 = 0.f, q2 = 0.f, q3 = 0.f;
            #pragma unroll
            for (int c = 0; c < 8; c++) {
                uint4 v = tn[c];                         // dims [8c, 8c+7], factor c>>1
                float2 ta = __half22float2(*reinterpret_cast<__half2*>(&v.x));
                float2 tb = __half22float2(*reinterpret_cast<__half2*>(&v.y));
                float2 tc = __half22float2(*reinterpret_cast<__half2*>(&v.z));
                float2 td = __half22float2(*reinterpret_cast<__half2*>(&v.w));
                float4 h0 = hp4[2 * c];
                float4 h1 = hp4[2 * c + 1];
                float qq = h0.x*ta.x + h0.y*ta.y + h0.z*tb.x + h0.w*tb.y
                         + h1.x*tc.x + h1.y*tc.y + h1.z*td.x + h1.w*td.y;
                if ((c >> 1) == 0) q0 += qq;
                else if ((c >> 1) == 1) q1 += qq;
                else if ((c >> 1) == 2) q2 += qq;
                else q3 += qq;
            }
            float4 An = Ap[j];
            An.x += q0; An.y += q1; An.z += q2; An.w += q3;
            float m  = fmaxf(fmaxf(An.x, An.y), fmaxf(An.z, An.w));
            float e0 = __expf(An.x - m), e1 = __expf(An.y - m);
            float e2 = __expf(An.z - m), e3 = __expf(An.w - m);
            float inv = 1.0f / (e0 + e1 + e2 + e3);
            Ap[j] = An;
            float4 nA = make_float4(e0 * inv, e1 * inv, e2 * inv, e3 * inv);
            normAo[j] = nA;
            dval.x += nA.x; dval.y += nA.y; dval.z += nA.z; dval.w += nA.w;
        }
    }
    // reduce dval across warp -> all lanes hold the node's dval per factor
    #pragma unroll
    for (int o = 16; o >= 1; o >>= 1) {
        dval.x += __shfl_xor_sync(0xffffffffu, dval.x, o);
        dval.y += __shfl_xor_sync(0xffffffffu, dval.y, o);
        dval.z += __shfl_xor_sync(0xffffffffu, dval.z, o);
        dval.w += __shfl_xor_sync(0xffffffffu, dval.w, o);
    }
    float4 dN = make_float4(rsqrtf(fmaxf(dval.x, 1e-8f)),
                            rsqrtf(fmaxf(dval.y, 1e-8f)),
                            rsqrtf(fmaxf(dval.z, 1e-8f)),
                            rsqrtf(fmaxf(dval.w, 1e-8f)));
    if (lane == 0) dinvN[w] = dN;
    float dNf = (f == 0) ? dN.x : (f == 1) ? dN.y : (f == 2) ? dN.z : dN.w;

    if (mode == 1) {
        // next layer's ego row == acc: write prescaled egoS and Tn directly
        egoSN[w * 32 + lane] = pack_h2(acc.x * dNf, acc.y * dNf);
        TnN[w * 32 + lane]   = pack_h2(tanhf(acc.x * hinv), tanhf(acc.y * hinv));
    } else {
        // same layer: egoS_next = layer ego * dinvN
        float2 src = reinterpret_cast<const float2*>(ego + w * kD)[lane];
        egoSN[w * 32 + lane] = pack_h2(src.x * dNf, src.y * dNf);
    }
}

// ---------------- host driver ----------------
extern "C" void kernel_launch(void* const* d_in, const int* in_sizes, int n_in,
                              void* d_out, int out_size) {
    const float* user = (const float*)d_in[0];
    const float* item = (const float*)d_in[1];
    const int*   hl   = (const int*)d_in[2];
    const int*   tl   = (const int*)d_in[3];
    float* out = (float*)d_out;

    const int TB = 256;
    k_init_ego<<<(kN * kD + TB - 1) / TB, TB>>>(user, item);   // + cnt zeroing
    k_count<<<(kE + TB - 1) / TB, TB>>>(hl);
    k_chunk_reduce<<<kNChunk, TB>>>();
    k_bsum_scan<<<1, 32>>>();
    k_chunk_scan<<<kNChunk, TB>>>();                           // + dinv0
    k_fill<<<(kE + TB - 1) / TB, TB>>>(hl, tl);
    k_tail0<<<(kN * 4 + TB - 1) / TB, TB>>>();                 // Tn0, egoS0 = buf0*dinvA

    const int FG = kN / 8;   // 8 warps / block
    // L0it0: read egoS0/Tn0/dinvA; write dinvB, egoS1 = buf0*dinvB
    k_fused<<<FG, TB>>>(0, 0, 0, 0, 0, out);
    // L0it1: read egoS1/Tn0/dinvB; write dinvA, egoS0 = acc*dinvA, Tn1 = tanh(acc*hinv); fe->buf1
    k_fused<<<FG, TB>>>(0, 1, 1, 0, 1, out);
    // L1it0: read egoS0/Tn1/dinvA; write dinvB, egoS1 = buf1*dinvB
    k_fused<<<FG, TB>>>(1, 0, 0, 1, 0, out);
    // L1it1: final output; read egoS1/dinvB
    k_fused<<<FG, TB>>>(1, 1, 1, 1, 2, out);
    (void)in_sizes; (void)n_in; (void)out_size;
}

// round 13
// speedup vs baseline: 1.5403x; 1.0045x over previous
#include <cuda_runtime.h>
#include <cuda_fp16.h>
#include <cuda_bf16.h>

namespace {
constexpr int kNUser = 50000;
constexpr int kN     = 80000;      // total nodes
constexpr int kE     = 1000000;    // 2 * NNZ symmetric edges
constexpr int kD     = 64;
constexpr int kChunk = 1024;
constexpr int kNChunk = (kN + kChunk - 1) / kChunk;   // 79
}

// ---------------- device scratch (static, no allocation) ----------------
__device__ float    g_A[kE * 4];        // routing logits, CSR-slot order
__device__ float    g_normA[kE * 4];    // softmax(A), CSR-slot order
__device__ float    g_buf0[kN * kD];    // initial ego (layer-0 input; never overwritten)
__device__ float    g_buf1[kN * kD];    // layer-0 output = layer-1 input
__device__ unsigned g_egoS0[kN * 32];   // prescaled ego, fp16 x2, ping (128B/node)
__device__ unsigned g_egoS1[kN * 32];   // pong
__device__ unsigned g_Tn0[kN * 32];     // tanh(normalized chunks), fp16 x2, ping
__device__ unsigned g_Tn1[kN * 32];     // pong
__device__ float    g_dinvA[kN * 4];    // 1/sqrt(degree-weight), ping
__device__ float    g_dinvB[kN * 4];    // pong
__device__ int      g_ptr[kN + 1];      // CSR row pointers (by head)
__device__ int      g_cnt[kN];          // histogram / fill counters
__device__ int      g_csr_t[kE];        // tail node per CSR slot
__device__ int      g_bsum[kNChunk];    // per-chunk sums for multi-block scan
__device__ int      g_red_done;         // last-block-done counter (self-resetting)

__device__ __forceinline__ unsigned pack_h2(float a, float b) {
    __half2 h = __floats2half2_rn(a, b);
    return *reinterpret_cast<unsigned*>(&h);
}

// ---------------- init (+ cnt zeroing folded in) ----------------
__global__ void k_init_ego(const float* __restrict__ user, const float* __restrict__ item) {
    int i = blockIdx.x * blockDim.x + threadIdx.x;
    if (i >= kN * kD) return;
    g_buf0[i] = (i < kNUser * kD) ? user[i] : item[i - kNUser * kD];
    if (i < kN) g_cnt[i] = 0;
}

// ---------------- CSR build ----------------
__global__ void k_count(const int* __restrict__ h) {
    int e = blockIdx.x * blockDim.x + threadIdx.x;
    if (e >= kE) return;
    atomicAdd(&g_cnt[h[e]], 1);
}

// chunk reduce + (last block) scan of the 79 block sums
__global__ void k_chunk_reduce() {            // kNChunk blocks x 256
    __shared__ int wsum[8];
    __shared__ int lastFlag;
    const int lane = threadIdx.x & 31, wrp = threadIdx.x >> 5;
    int base = blockIdx.x * kChunk + (int)threadIdx.x * 4;
    int s = 0;
    #pragma unroll
    for (int k = 0; k < 4; k++) { int i = base + k; if (i < kN) s += g_cnt[i]; }
    #pragma unroll
    for (int o = 16; o >= 1; o >>= 1) s += __shfl_xor_sync(0xffffffffu, s, o);
    if (lane == 0) wsum[wrp] = s;
    __syncthreads();
    if (threadIdx.x == 0) {
        int t = 0;
        #pragma unroll
        for (int k = 0; k < 8; k++) t += wsum[k];
        g_bsum[blockIdx.x] = t;
        __threadfence();
        int v = atomicAdd(&g_red_done, 1);
        lastFlag = (v == (int)gridDim.x - 1) ? 1 : 0;
    }
    __syncthreads();
    if (lastFlag && threadIdx.x < 32) {
        // 32-lane exclusive scan of g_bsum[0..kNChunk)
        int carry = 0;
        for (int b2 = 0; b2 < kNChunk; b2 += 32) {
            int i = b2 + (int)threadIdx.x;
            int v = (i < kNChunk) ? __ldcg(&g_bsum[i]) : 0;
            int x = v;
            #pragma unroll
            for (int o = 1; o < 32; o <<= 1) {
                int y = __shfl_up_sync(0xffffffffu, x, o);
                if ((int)threadIdx.x >= o) x += y;
            }
            if (i < kNChunk) g_bsum[i] = carry + x - v;   // exclusive
            carry += __shfl_sync(0xffffffffu, x, 31);
        }
        if (threadIdx.x == 0) { g_ptr[kN] = carry; g_red_done = 0; }
    }
}

// chunk scan + dinv0 folded in (degree is in registers here)
__global__ void k_chunk_scan() {              // kNChunk blocks x 256
    __shared__ int wsum[8];
    const int lane = threadIdx.x & 31, wrp = threadIdx.x >> 5;
    int base = blockIdx.x * kChunk + (int)threadIdx.x * 4;
    int v0 = 0, v1 = 0, v2 = 0, v3 = 0;
    if (base + 3 < kN) {
        int4 v = *reinterpret_cast<const int4*>(&g_cnt[base]);
        v0 = v.x; v1 = v.y; v2 = v.z; v3 = v.w;
    } else {
        if (base + 0 < kN) v0 = g_cnt[base + 0];
        if (base + 1 < kN) v1 = g_cnt[base + 1];
        if (base + 2 < kN) v2 = g_cnt[base + 2];
        if (base + 3 < kN) v3 = g_cnt[base + 3];
    }
    int tot = v0 + v1 + v2 + v3;
    int x = tot;
    #pragma unroll
    for (int o = 1; o < 32; o <<= 1) {
        int y = __shfl_up_sync(0xffffffffu, x, o);
        if (lane >= o) x += y;
    }
    if (lane == 31) wsum[wrp] = x;
    __syncthreads();
    if (wrp == 0 && lane < 8) {
        int s = wsum[lane], xs = s;
        #pragma unroll
        for (int o = 1; o < 8; o <<= 1) {
            int y = __shfl_up_sync(0xffu, xs, o);
            if (lane >= o) xs += y;
        }
        wsum[lane] = xs - s;
    }
    __syncthreads();
    int ex = g_bsum[blockIdx.x] + wsum[wrp] + (x - tot);
    int vv[4] = {v0, v1, v2, v3};
    int pre[4] = {0, v0, v0 + v1, v0 + v1 + v2};
    #pragma unroll
    for (int k = 0; k < 4; k++) {
        int n = base + k;
        if (n < kN) {
            g_ptr[n] = ex + pre[k];
            g_cnt[n] = 0;
            float di = rsqrtf(fmaxf(0.25f * (float)vv[k], 1e-8f));
            reinterpret_cast<float4*>(g_dinvA)[n] = make_float4(di, di, di, di);
        }
    }
}

// fill CSR + A/normA init (slot order) + layer-0 tail prep (Tn0, egoS0), one kernel
__global__ void k_fill_tail(const int* __restrict__ h, const int* __restrict__ t) {
    int i = blockIdx.x * blockDim.x + threadIdx.x;
    if (i < kE) {
        int hn   = h[i];
        int slot = g_ptr[hn] + atomicAdd(&g_cnt[hn], 1);
        g_csr_t[slot] = t[i];
        reinterpret_cast<float4*>(g_A)[slot]     = make_float4(1.f, 1.f, 1.f, 1.f);
        reinterpret_cast<float4*>(g_normA)[slot] = make_float4(.25f, .25f, .25f, .25f);
    }
    if (i < kN * 4) {
        const float4* src = reinterpret_cast<const float4*>(g_buf0) + i * 4;
        float4 v0 = src[0], v1 = src[1], v2 = src[2], v3 = src[3];
        float ss = v0.x*v0.x + v0.y*v0.y + v0.z*v0.z + v0.w*v0.w
                 + v1.x*v1.x + v1.y*v1.y + v1.z*v1.z + v1.w*v1.w
                 + v2.x*v2.x + v2.y*v2.y + v2.z*v2.z + v2.w*v2.w
                 + v3.x*v3.x + v3.y*v3.y + v3.z*v3.z + v3.w*v3.w;
        float inv = 1.0f / fmaxf(sqrtf(ss), 1e-12f);
        uint4 u0, u1;
        u0.x = pack_h2(tanhf(v0.x*inv), tanhf(v0.y*inv));
        u0.y = pack_h2(tanhf(v0.z*inv), tanhf(v0.w*inv));
        u0.z = pack_h2(tanhf(v1.x*inv), tanhf(v1.y*inv));
        u0.w = pack_h2(tanhf(v1.z*inv), tanhf(v1.w*inv));
        u1.x = pack_h2(tanhf(v2.x*inv), tanhf(v2.y*inv));
        u1.y = pack_h2(tanhf(v2.z*inv), tanhf(v2.w*inv));
        u1.z = pack_h2(tanhf(v3.x*inv), tanhf(v3.y*inv));
        u1.w = pack_h2(tanhf(v3.z*inv), tanhf(v3.w*inv));
        reinterpret_cast<uint4*>(g_Tn0)[i * 2]     = u0;
        reinterpret_cast<uint4*>(g_Tn0)[i * 2 + 1] = u1;
        float di = g_dinvA[i];
        uint4 s0, s1;
        s0.x = pack_h2(v0.x*di, v0.y*di);
        s0.y = pack_h2(v0.z*di, v0.w*di);
        s0.z = pack_h2(v1.x*di, v1.y*di);
        s0.w = pack_h2(v1.z*di, v1.w*di);
        s1.x = pack_h2(v2.x*di, v2.y*di);
        s1.y = pack_h2(v2.z*di, v2.w*di);
        s1.z = pack_h2(v3.x*di, v3.y*di);
        s1.w = pack_h2(v3.z*di, v3.w*di);
        reinterpret_cast<uint4*>(g_egoS0)[i * 2]     = s0;
        reinterpret_cast<uint4*>(g_egoS0)[i * 2 + 1] = s1;
    }
}

// ---------------- fused iteration ----------------
// one warp per node. MP: lane owns dims [2l,2l+1] (one __half2), factor f = lane>>3,
// smem-staged edge weights; egoS row = 128B fp16 -> 1 line per edge.
// Routing: lane-per-edge, per-lane softmax; tail id from sm_t when deg<=32
// (kills the dependent csr_t LDG on the routing critical path).
// Epilogue writes next-iteration egoS (and, in mode 1, next-layer Tn) to the
// OTHER buffer (race-free double buffering).
// mode: 0 = routing, egoS_next = ego[w]*dinvN
//       1 = routing + fe write, egoS_next = acc*dinvN, Tn_next = tanh(acc*hinv)
//       2 = final output
__global__ void __launch_bounds__(256) k_fused(
        int sel_in, int dsel, int esel, int tsel, int mode, float* __restrict__ out)
{
    __shared__ int    sm_t[8][32];
    __shared__ float  sm_wT[8][4][33];
    __shared__ float2 sm_h[8][32];      // normalized head (64 floats / warp)

    const int warp = threadIdx.x >> 5;
    const int lane = threadIdx.x & 31;
    const int w = blockIdx.x * 8 + warp;
    const int f = lane >> 3;

    const float*    ego    = sel_in ? g_buf1 : g_buf0;
    float*          fe     = sel_in ? g_buf0 : g_buf1;   // only written in mode 1 (sel_in=0)
    const unsigned* egoSC  = esel ? g_egoS1 : g_egoS0;
    unsigned*       egoSN  = esel ? g_egoS0 : g_egoS1;
    const unsigned* TnC    = tsel ? g_Tn1 : g_Tn0;
    unsigned*       TnN    = tsel ? g_Tn0 : g_Tn1;
    const float4*   dinvC  = reinterpret_cast<const float4*>(dsel ? g_dinvB : g_dinvA);
    float4*         dinvN  = reinterpret_cast<float4*>(dsel ? g_dinvA : g_dinvB);
    const float4*   normA  = reinterpret_cast<const float4*>(g_normA);
    float4*         normAo = reinterpret_cast<float4*>(g_normA);
    float4*         Ap     = reinterpret_cast<float4*>(g_A);

    const int s = g_ptr[w], e = g_ptr[w + 1];
    const bool single = (e - s) <= 32;     // sm_t holds ALL tails after MP

    // ---- message passing ----
    float2 acc = make_float2(0.f, 0.f);
    for (int base = s; base < e; base += 32) {
        int j = base + lane;
        bool valid = j < e;
        int t = valid ? g_csr_t[j] : 0;
        float4 na = valid ? normA[j] : make_float4(0.f, 0.f, 0.f, 0.f);
        sm_t[warp][lane] = t;
        sm_wT[warp][0][lane] = na.x;
        sm_wT[warp][1][lane] = na.y;
        sm_wT[warp][2][lane] = na.z;
        sm_wT[warp][3][lane] = na.w;
        __syncwarp();
        int cnt = min(32, e - base);
        #pragma unroll 8
        for (int k = 0; k < cnt; k++) {
            int   tk = sm_t[warp][k];
            float wk = sm_wT[warp][f][k];
            float2 ev = __half22float2(*reinterpret_cast<const __half2*>(&egoSC[tk * 32 + lane]));
            acc.x += wk * ev.x;
            acc.y += wk * ev.y;
        }
        __syncwarp();
    }
    {
        float4 dh = dinvC[w];
        float ds = (f == 0) ? dh.x : (f == 1) ? dh.y : (f == 2) ? dh.z : dh.w;
        acc.x *= ds; acc.y *= ds;
    }

    if (mode == 2) {
        // final: out = (initial_ego(buf0) + layer1_input(buf1) + fe)/3
        float2 a = reinterpret_cast<const float2*>(g_buf0 + w * kD)[lane];
        float2 b = reinterpret_cast<const float2*>(ego + w * kD)[lane];
        float2 o;
        o.x = (a.x + b.x + acc.x) * (1.0f / 3.0f);
        o.y = (a.y + b.y + acc.y) * (1.0f / 3.0f);
        reinterpret_cast<float2*>(out + w * kD)[lane] = o;
        return;
    }

    if (mode == 1)
        reinterpret_cast<float2*>(fe + w * kD)[lane] = acc;

    // ---- head inverse norm (per 8-lane group = one factor) ----
    float ss = acc.x * acc.x + acc.y * acc.y;
    #pragma unroll
    for (int o = 4; o >= 1; o >>= 1) ss += __shfl_xor_sync(0xffffffffu, ss, o);
    const float hinv = 1.0f / fmaxf(sqrtf(ss), 1e-12f);
    sm_h[warp][lane] = make_float2(acc.x * hinv, acc.y * hinv);
    __syncwarp();

    // ---- routing: lane-per-edge, per-lane softmax, fp16 Tn row ----
    const float4* hp4 = reinterpret_cast<const float4*>(&sm_h[warp][0]);
    float4 dval = make_float4(0.f, 0.f, 0.f, 0.f);
    for (int base = s; base < e; base += 32) {
        int j = base + lane;
        if (j < e) {
            int t = single ? sm_t[warp][lane] : g_csr_t[j];
            const uint4* tn = reinterpret_cast<const uint4*>(TnC) + t * 8;
            float q0 = 0.f, q1 = 0.f, q2 = 0.f, q3 = 0.f;
            #pragma unroll
            for (int c = 0; c < 8; c++) {
                uint4 v = tn[c];                         // dims [8c, 8c+7], factor c>>1
                float2 ta = __half22float2(*reinterpret_cast<__half2*>(&v.x));
                float2 tb = __half22float2(*reinterpret_cast<__half2*>(&v.y));
                float2 tc = __half22float2(*reinterpret_cast<__half2*>(&v.z));
                float2 td = __half22float2(*reinterpret_cast<__half2*>(&v.w));
                float4 h0 = hp4[2 * c];
                float4 h1 = hp4[2 * c + 1];
                float qq = h0.x*ta.x + h0.y*ta.y + h0.z*tb.x + h0.w*tb.y
                         + h1.x*tc.x + h1.y*tc.y + h1.z*td.x + h1.w*td.y;
                if ((c >> 1) == 0) q0 += qq;
                else if ((c >> 1) == 1) q1 += qq;
                else if ((c >> 1) == 2) q2 += qq;
                else q3 += qq;
            }
            float4 An = Ap[j];
            An.x += q0; An.y += q1; An.z += q2; An.w += q3;
            float m  = fmaxf(fmaxf(An.x, An.y), fmaxf(An.z, An.w));
            float e0 = __expf(An.x - m), e1 = __expf(An.y - m);
            float e2 = __expf(An.z - m), e3 = __expf(An.w - m);
            float inv = 1.0f / (e0 + e1 + e2 + e3);
            Ap[j] = An;
            float4 nA = make_float4(e0 * inv, e1 * inv, e2 * inv, e3 * inv);
            normAo[j] = nA;
            dval.x += nA.x; dval.y += nA.y; dval.z += nA.z; dval.w += nA.w;
        }
    }
    // reduce dval across warp -> all lanes hold the node's dval per factor
    #pragma unroll
    for (int o = 16; o >= 1; o >>= 1) {
        dval.x += __shfl_xor_sync(0xffffffffu, dval.x, o);
        dval.y += __shfl_xor_sync(0xffffffffu, dval.y, o);
        dval.z += __shfl_xor_sync(0xffffffffu, dval.z, o);
        dval.w += __shfl_xor_sync(0xffffffffu, dval.w, o);
    }
    float4 dN = make_float4(rsqrtf(fmaxf(dval.x, 1e-8f)),
                            rsqrtf(fmaxf(dval.y, 1e-8f)),
                            rsqrtf(fmaxf(dval.z, 1e-8f)),
                            rsqrtf(fmaxf(dval.w, 1e-8f)));
    if (lane == 0) dinvN[w] = dN;
    float dNf = (f == 0) ? dN.x : (f == 1) ? dN.y : (f == 2) ? dN.z : dN.w;

    if (mode == 1) {
        // next layer's ego row == acc: write prescaled egoS and Tn directly
        egoSN[w * 32 + lane] = pack_h2(acc.x * dNf, acc.y * dNf);
        TnN[w * 32 + lane]   = pack_h2(tanhf(acc.x * hinv), tanhf(acc.y * hinv));
    } else {
        // same layer: egoS_next = layer ego * dinvN
        float2 src = reinterpret_cast<const float2*>(ego + w * kD)[lane];
        egoSN[w * 32 + lane] = pack_h2(src.x * dNf, src.y * dNf);
    }
}

// ---------------- host driver ----------------
extern "C" void kernel_launch(void* const* d_in, const int* in_sizes, int n_in,
                              void* d_out, int out_size) {
    const float* user = (const float*)d_in[0];
    const float* item = (const float*)d_in[1];
    const int*   hl   = (const int*)d_in[2];
    const int*   tl   = (const int*)d_in[3];
    float* out = (float*)d_out;

    const int TB = 256;
    k_init_ego<<<(kN * kD + TB - 1) / TB, TB>>>(user, item);   // + cnt zeroing
    k_count<<<(kE + TB - 1) / TB, TB>>>(hl);
    k_chunk_reduce<<<kNChunk, TB>>>();                         // + bsum scan (last block)
    k_chunk_scan<<<kNChunk, TB>>>();                           // + dinv0
    k_fill_tail<<<(kE + TB - 1) / TB, TB>>>(hl, tl);           // + Tn0/egoS0 prep

    const int FG = kN / 8;   // 8 warps / block
    // L0it0: read egoS0/Tn0/dinvA; write dinvB, egoS1 = buf0*dinvB
    k_fused<<<FG, TB>>>(0, 0, 0, 0, 0, out);
    // L0it1: read egoS1/Tn0/dinvB; write dinvA, egoS0 = acc*dinvA, Tn1 = tanh(acc*hinv); fe->buf1
    k_fused<<<FG, TB>>>(0, 1, 1, 0, 1, out);
    // L1it0: read egoS0/Tn1/dinvA; write dinvB, egoS1 = buf1*dinvB
    k_fused<<<FG, TB>>>(1, 0, 0, 1, 0, out);
    // L1it1: final output; read egoS1/dinvB
    k_fused<<<FG, TB>>>(1, 1, 1, 1, 2, out);
    (void)in_sizes; (void)n_in; (void)out_size;
}

// round 15
// speedup vs baseline: 1.7921x; 1.1635x over previous
#include <cuda_runtime.h>
#include <cuda_fp16.h>
#include <cuda_bf16.h>

namespace {
constexpr int kNUser = 50000;
constexpr int kN     = 80000;      // total nodes
constexpr int kE     = 1000000;    // 2 * NNZ symmetric edges
constexpr int kD     = 64;
constexpr int kChunk = 1024;
constexpr int kNChunk = (kN + kChunk - 1) / kChunk;   // 79
}

// ---------------- device scratch (static, no allocation) ----------------
__device__ float    g_A[kE * 4];        // routing logits, CSR-slot order
__device__ float    g_normA[kE * 4];    // softmax(A), CSR-slot order
__device__ float    g_buf0[kN * kD];    // initial ego (layer-0 input; never overwritten)
__device__ float    g_buf1[kN * kD];    // layer-0 output = layer-1 input
__device__ unsigned g_egoS0[kN * 32];   // prescaled ego, fp16 x2, ping (128B/node)
__device__ unsigned g_egoS1[kN * 32];   // pong
__device__ unsigned g_Tn8_0[kN * 16];   // tanh(normalized chunks), int8, ping (64B/node)
__device__ unsigned g_Tn8_1[kN * 16];   // pong
__device__ float    g_dinvA[kN * 4];    // 1/sqrt(degree-weight), ping
__device__ float    g_dinvB[kN * 4];    // pong
__device__ int      g_ptr[kN + 1];      // CSR row pointers (by head)
__device__ int      g_cnt[kN];          // histogram / fill counters
__device__ int      g_csr_t[kE];        // tail node per CSR slot
__device__ int      g_bsum[kNChunk];    // per-chunk sums for multi-block scan
__device__ int      g_red_done;         // last-block-done counter (self-resetting)

__device__ __forceinline__ unsigned pack_h2(float a, float b) {
    __half2 h = __floats2half2_rn(a, b);
    return *reinterpret_cast<unsigned*>(&h);
}
__device__ __forceinline__ int q8(float x) {           // x in [-1,1]
    return __float2int_rn(x * 127.0f);
}
__device__ __forceinline__ unsigned pack_b4(int a, int b, int c, int d) {
    return (unsigned)(a & 0xFF) | ((unsigned)(b & 0xFF) << 8) |
           ((unsigned)(c & 0xFF) << 16) | ((unsigned)(d & 0xFF) << 24);
}

// ---------------- init (+ cnt zeroing folded in) ----------------
__global__ void k_init_ego(const float* __restrict__ user, const float* __restrict__ item) {
    int i = blockIdx.x * blockDim.x + threadIdx.x;
    if (i >= kN * kD) return;
    g_buf0[i] = (i < kNUser * kD) ? user[i] : item[i - kNUser * kD];
    if (i < kN) g_cnt[i] = 0;
}

// ---------------- CSR build ----------------
__global__ void k_count(const int* __restrict__ h) {
    int e = blockIdx.x * blockDim.x + threadIdx.x;
    if (e >= kE) return;
    atomicAdd(&g_cnt[h[e]], 1);
}

// chunk reduce + (last block) scan of the 79 block sums
__global__ void k_chunk_reduce() {            // kNChunk blocks x 256
    __shared__ int wsum[8];
    __shared__ int lastFlag;
    const int lane = threadIdx.x & 31, wrp = threadIdx.x >> 5;
    int base = blockIdx.x * kChunk + (int)threadIdx.x * 4;
    int s = 0;
    #pragma unroll
    for (int k = 0; k < 4; k++) { int i = base + k; if (i < kN) s += g_cnt[i]; }
    #pragma unroll
    for (int o = 16; o >= 1; o >>= 1) s += __shfl_xor_sync(0xffffffffu, s, o);
    if (lane == 0) wsum[wrp] = s;
    __syncthreads();
    if (threadIdx.x == 0) {
        int t = 0;
        #pragma unroll
        for (int k = 0; k < 8; k++) t += wsum[k];
        g_bsum[blockIdx.x] = t;
        __threadfence();
        int v = atomicAdd(&g_red_done, 1);
        lastFlag = (v == (int)gridDim.x - 1) ? 1 : 0;
    }
    __syncthreads();
    if (lastFlag && threadIdx.x < 32) {
        int carry = 0;
        for (int b2 = 0; b2 < kNChunk; b2 += 32) {
            int i = b2 + (int)threadIdx.x;
            int v = (i < kNChunk) ? __ldcg(&g_bsum[i]) : 0;
            int x = v;
            #pragma unroll
            for (int o = 1; o < 32; o <<= 1) {
                int y = __shfl_up_sync(0xffffffffu, x, o);
                if ((int)threadIdx.x >= o) x += y;
            }
            if (i < kNChunk) g_bsum[i] = carry + x - v;   // exclusive
            carry += __shfl_sync(0xffffffffu, x, 31);
        }
        if (threadIdx.x == 0) { g_ptr[kN] = carry; g_red_done = 0; }
    }
}

// chunk scan + dinv0 folded in (degree is in registers here)
__global__ void k_chunk_scan() {              // kNChunk blocks x 256
    __shared__ int wsum[8];
    const int lane = threadIdx.x & 31, wrp = threadIdx.x >> 5;
    int base = blockIdx.x * kChunk + (int)threadIdx.x * 4;
    int v0 = 0, v1 = 0, v2 = 0, v3 = 0;
    if (base + 3 < kN) {
        int4 v = *reinterpret_cast<const int4*>(&g_cnt[base]);
        v0 = v.x; v1 = v.y; v2 = v.z; v3 = v.w;
    } else {
        if (base + 0 < kN) v0 = g_cnt[base + 0];
        if (base + 1 < kN) v1 = g_cnt[base + 1];
        if (base + 2 < kN) v2 = g_cnt[base + 2];
        if (base + 3 < kN) v3 = g_cnt[base + 3];
    }
    int tot = v0 + v1 + v2 + v3;
    int x = tot;
    #pragma unroll
    for (int o = 1; o < 32; o <<= 1) {
        int y = __shfl_up_sync(0xffffffffu, x, o);
        if (lane >= o) x += y;
    }
    if (lane == 31) wsum[wrp] = x;
    __syncthreads();
    if (wrp == 0 && lane < 8) {
        int s = wsum[lane], xs = s;
        #pragma unroll
        for (int o = 1; o < 8; o <<= 1) {
            int y = __shfl_up_sync(0xffu, xs, o);
            if (lane >= o) xs += y;
        }
        wsum[lane] = xs - s;
    }
    __syncthreads();
    int ex = g_bsum[blockIdx.x] + wsum[wrp] + (x - tot);
    int vv[4] = {v0, v1, v2, v3};
    int pre[4] = {0, v0, v0 + v1, v0 + v1 + v2};
    #pragma unroll
    for (int k = 0; k < 4; k++) {
        int n = base + k;
        if (n < kN) {
            g_ptr[n] = ex + pre[k];
            g_cnt[n] = 0;
            float di = rsqrtf(fmaxf(0.25f * (float)vv[k], 1e-8f));
            reinterpret_cast<float4*>(g_dinvA)[n] = make_float4(di, di, di, di);
        }
    }
}

// fill CSR + A/normA init (slot order) + layer-0 tail prep (Tn8_0, egoS0), one kernel
__global__ void k_fill_tail(const int* __restrict__ h, const int* __restrict__ t) {
    int i = blockIdx.x * blockDim.x + threadIdx.x;
    if (i < kE) {
        int hn   = h[i];
        int slot = g_ptr[hn] + atomicAdd(&g_cnt[hn], 1);
        g_csr_t[slot] = t[i];
        reinterpret_cast<float4*>(g_A)[slot]     = make_float4(1.f, 1.f, 1.f, 1.f);
        reinterpret_cast<float4*>(g_normA)[slot] = make_float4(.25f, .25f, .25f, .25f);
    }
    if (i < kN * 4) {
        const float4* src = reinterpret_cast<const float4*>(g_buf0) + i * 4;
        float4 v0 = src[0], v1 = src[1], v2 = src[2], v3 = src[3];
        float ss = v0.x*v0.x + v0.y*v0.y + v0.z*v0.z + v0.w*v0.w
                 + v1.x*v1.x + v1.y*v1.y + v1.z*v1.z + v1.w*v1.w
                 + v2.x*v2.x + v2.y*v2.y + v2.z*v2.z + v2.w*v2.w
                 + v3.x*v3.x + v3.y*v3.y + v3.z*v3.z + v3.w*v3.w;
        float inv = 1.0f / fmaxf(sqrtf(ss), 1e-12f);
        uint4 tq;
        tq.x = pack_b4(q8(tanhf(v0.x*inv)), q8(tanhf(v0.y*inv)), q8(tanhf(v0.z*inv)), q8(tanhf(v0.w*inv)));
        tq.y = pack_b4(q8(tanhf(v1.x*inv)), q8(tanhf(v1.y*inv)), q8(tanhf(v1.z*inv)), q8(tanhf(v1.w*inv)));
        tq.z = pack_b4(q8(tanhf(v2.x*inv)), q8(tanhf(v2.y*inv)), q8(tanhf(v2.z*inv)), q8(tanhf(v2.w*inv)));
        tq.w = pack_b4(q8(tanhf(v3.x*inv)), q8(tanhf(v3.y*inv)), q8(tanhf(v3.z*inv)), q8(tanhf(v3.w*inv)));
        reinterpret_cast<uint4*>(g_Tn8_0)[i] = tq;
        float di = g_dinvA[i];
        uint4 s0, s1;
        s0.x = pack_h2(v0.x*di, v0.y*di);
        s0.y = pack_h2(v0.z*di, v0.w*di);
        s0.z = pack_h2(v1.x*di, v1.y*di);
        s0.w = pack_h2(v1.z*di, v1.w*di);
        s1.x = pack_h2(v2.x*di, v2.y*di);
        s1.y = pack_h2(v2.z*di, v2.w*di);
        s1.z = pack_h2(v3.x*di, v3.y*di);
        s1.w = pack_h2(v3.z*di, v3.w*di);
        reinterpret_cast<uint4*>(g_egoS0)[i * 2]     = s0;
        reinterpret_cast<uint4*>(g_egoS0)[i * 2 + 1] = s1;
    }
}

// ---------------- fused iteration ----------------
// one warp per node. MP: lane owns dims [2l,2l+1] (one __half2), factor f = lane>>3,
// smem-staged edge weights; egoS row = 128B fp16 -> 1 line per edge.
// Routing: lane-per-edge; Tn row = 64B int8 -> 4xLDG.128 + 16 dp4a per edge;
// head quantized to int8 in smem once per node; per-lane softmax.
// Epilogue writes next-iteration egoS (and, in mode 1, next-layer Tn8) to the
// OTHER buffer (race-free double buffering).
// mode: 0 = routing, egoS_next = ego[w]*dinvN
//       1 = routing + fe write, egoS_next = acc*dinvN, Tn8_next = q8(tanh(acc*hinv))
//       2 = final output
__global__ void __launch_bounds__(256) k_fused(
        int sel_in, int dsel, int esel, int tsel, int mode, float* __restrict__ out)
{
    __shared__ int            sm_t[8][32];
    __shared__ float          sm_wT[8][4][33];
    __shared__ unsigned short sm_hq[8][32];   // int8-quantized head (64 bytes / warp)

    const int warp = threadIdx.x >> 5;
    const int lane = threadIdx.x & 31;
    const int w = blockIdx.x * 8 + warp;
    const int f = lane >> 3;

    const float*    ego    = sel_in ? g_buf1 : g_buf0;
    float*          fe     = sel_in ? g_buf0 : g_buf1;   // only written in mode 1 (sel_in=0)
    const unsigned* egoSC  = esel ? g_egoS1 : g_egoS0;
    unsigned*       egoSN  = esel ? g_egoS0 : g_egoS1;
    const unsigned* Tn8C   = tsel ? g_Tn8_1 : g_Tn8_0;
    unsigned*       Tn8N   = tsel ? g_Tn8_0 : g_Tn8_1;
    const float4*   dinvC  = reinterpret_cast<const float4*>(dsel ? g_dinvB : g_dinvA);
    float4*         dinvN  = reinterpret_cast<float4*>(dsel ? g_dinvA : g_dinvB);
    const float4*   normA  = reinterpret_cast<const float4*>(g_normA);
    float4*         normAo = reinterpret_cast<float4*>(g_normA);
    float4*         Ap     = reinterpret_cast<float4*>(g_A);

    const int s = g_ptr[w], e = g_ptr[w + 1];
    const bool single = (e - s) <= 32;     // sm_t holds ALL tails after MP

    // ---- message passing ----
    float2 acc = make_float2(0.f, 0.f);
    for (int base = s; base < e; base += 32) {
        int j = base + lane;
        bool valid = j < e;
        int t = valid ? g_csr_t[j] : 0;
        float4 na = valid ? normA[j] : make_float4(0.f, 0.f, 0.f, 0.f);
        sm_t[warp][lane] = t;
        sm_wT[warp][0][lane] = na.x;
        sm_wT[warp][1][lane] = na.y;
        sm_wT[warp][2][lane] = na.z;
        sm_wT[warp][3][lane] = na.w;
        __syncwarp();
        int cnt = min(32, e - base);
        #pragma unroll 8
        for (int k = 0; k < cnt; k++) {
            int   tk = sm_t[warp][k];
            float wk = sm_wT[warp][f][k];
            float2 ev = __half22float2(*reinterpret_cast<const __half2*>(&egoSC[tk * 32 + lane]));
            acc.x += wk * ev.x;
            acc.y += wk * ev.y;
        }
        __syncwarp();
    }
    {
        float4 dh = dinvC[w];
        float ds = (f == 0) ? dh.x : (f == 1) ? dh.y : (f == 2) ? dh.z : dh.w;
        acc.x *= ds; acc.y *= ds;
    }

    if (mode == 2) {
        // final: out = (initial_ego(buf0) + layer1_input(buf1) + fe)/3
        float2 a = reinterpret_cast<const float2*>(g_buf0 + w * kD)[lane];
        float2 b = reinterpret_cast<const float2*>(ego + w * kD)[lane];
        float2 o;
        o.x = (a.x + b.x + acc.x) * (1.0f / 3.0f);
        o.y = (a.y + b.y + acc.y) * (1.0f / 3.0f);
        reinterpret_cast<float2*>(out + w * kD)[lane] = o;
        return;
    }

    if (mode == 1)
        reinterpret_cast<float2*>(fe + w * kD)[lane] = acc;

    // ---- head inverse norm (per 8-lane group = one factor) + int8 quantize ----
    float ss = acc.x * acc.x + acc.y * acc.y;
    #pragma unroll
    for (int o = 4; o >= 1; o >>= 1) ss += __shfl_xor_sync(0xffffffffu, ss, o);
    const float hinv = 1.0f / fmaxf(sqrtf(ss), 1e-12f);
    {
        int bx = q8(acc.x * hinv);
        int by = q8(acc.y * hinv);
        sm_hq[warp][lane] = (unsigned short)((bx & 0xFF) | ((by & 0xFF) << 8));
    }
    __syncwarp();

    // ---- routing: lane-per-edge, int8 Tn row (64B) + dp4a, per-lane softmax ----
    const int* hq32 = reinterpret_cast<const int*>(&sm_hq[warp][0]);  // 16 words
    const float qscale = 1.0f / (127.0f * 127.0f);
    float4 dval = make_float4(0.f, 0.f, 0.f, 0.f);
    for (int base = s; base < e; base += 32) {
        int j = base + lane;
        if (j < e) {
            int t = single ? sm_t[warp][lane] : g_csr_t[j];
            const uint4* tn = reinterpret_cast<const uint4*>(Tn8C) + t * 4;
            int d0, d1, d2, d3;
            {
                uint4 v = tn[0];   // factor 0, dims 0..15
                d0 = __dp4a((int)v.x, hq32[0], 0);
                d0 = __dp4a((int)v.y, hq32[1], d0);
                d0 = __dp4a((int)v.z, hq32[2], d0);
                d0 = __dp4a((int)v.w, hq32[3], d0);
            }
            {
                uint4 v = tn[1];   // factor 1, dims 16..31
                d1 = __dp4a((int)v.x, hq32[4], 0);
                d1 = __dp4a((int)v.y, hq32[5], d1);
                d1 = __dp4a((int)v.z, hq32[6], d1);
                d1 = __dp4a((int)v.w, hq32[7], d1);
            }
            {
                uint4 v = tn[2];   // factor 2, dims 32..47
                d2 = __dp4a((int)v.x, hq32[8],  0);
                d2 = __dp4a((int)v.y, hq32[9],  d2);
                d2 = __dp4a((int)v.z, hq32[10], d2);
                d2 = __dp4a((int)v.w, hq32[11], d2);
            }
            {
                uint4 v = tn[3];   // factor 3, dims 48..63
                d3 = __dp4a((int)v.x, hq32[12], 0);
                d3 = __dp4a((int)v.y, hq32[13], d3);
                d3 = __dp4a((int)v.z, hq32[14], d3);
                d3 = __dp4a((int)v.w, hq32[15], d3);
            }
            float4 An = Ap[j];
            An.x += (float)d0 * qscale;
            An.y += (float)d1 * qscale;
            An.z += (float)d2 * qscale;
            An.w += (float)d3 * qscale;
            float m  = fmaxf(fmaxf(An.x, An.y), fmaxf(An.z, An.w));
            float e0 = __expf(An.x - m), e1 = __expf(An.y - m);
            float e2 = __expf(An.z - m), e3 = __expf(An.w - m);
            float inv = 1.0f / (e0 + e1 + e2 + e3);
            Ap[j] = An;
            float4 nA = make_float4(e0 * inv, e1 * inv, e2 * inv, e3 * inv);
            normAo[j] = nA;
            dval.x += nA.x; dval.y += nA.y; dval.z += nA.z; dval.w += nA.w;
        }
    }
    // reduce dval across warp -> all lanes hold the node's dval per factor
    #pragma unroll
    for (int o = 16; o >= 1; o >>= 1) {
        dval.x += __shfl_xor_sync(0xffffffffu, dval.x, o);
        dval.y += __shfl_xor_sync(0xffffffffu, dval.y, o);
        dval.z += __shfl_xor_sync(0xffffffffu, dval.z, o);
        dval.w += __shfl_xor_sync(0xffffffffu, dval.w, o);
    }
    float4 dN = make_float4(rsqrtf(fmaxf(dval.x, 1e-8f)),
                            rsqrtf(fmaxf(dval.y, 1e-8f)),
                            rsqrtf(fmaxf(dval.z, 1e-8f)),
                            rsqrtf(fmaxf(dval.w, 1e-8f)));
    if (lane == 0) dinvN[w] = dN;
    float dNf = (f == 0) ? dN.x : (f == 1) ? dN.y : (f == 2) ? dN.z : dN.w;

    if (mode == 1) {
        // next layer's ego row == acc: write prescaled egoS and quantized Tn directly
        egoSN[w * 32 + lane] = pack_h2(acc.x * dNf, acc.y * dNf);
        int bx = q8(tanhf(acc.x * hinv));
        int by = q8(tanhf(acc.y * hinv));
        reinterpret_cast<unsigned short*>(Tn8N)[w * 32 + lane] =
            (unsigned short)((bx & 0xFF) | ((by & 0xFF) << 8));
    } else {
        // same layer: egoS_next = layer ego * dinvN
        float2 src = reinterpret_cast<const float2*>(ego + w * kD)[lane];
        egoSN[w * 32 + lane] = pack_h2(src.x * dNf, src.y * dNf);
    }
}

// ---------------- host driver ----------------
extern "C" void kernel_launch(void* const* d_in, const int* in_sizes, int n_in,
                              void* d_out, int out_size) {
    const float* user = (const float*)d_in[0];
    const float* item = (const float*)d_in[1];
    const int*   hl   = (const int*)d_in[2];
    const int*   tl   = (const int*)d_in[3];
    float* out = (float*)d_out;

    const int TB = 256;
    k_init_ego<<<(kN * kD + TB - 1) / TB, TB>>>(user, item);   // + cnt zeroing
    k_count<<<(kE + TB - 1) / TB, TB>>>(hl);
    k_chunk_reduce<<<kNChunk, TB>>>();                         // + bsum scan (last block)
    k_chunk_scan<<<kNChunk, TB>>>();                           // + dinv0
    k_fill_tail<<<(kE + TB - 1) / TB, TB>>>(hl, tl);           // + Tn8_0/egoS0 prep

    const int FG = kN / 8;   // 8 warps / block
    // L0it0: read egoS0/Tn8_0/dinvA; write dinvB, egoS1 = buf0*dinvB
    k_fused<<<FG, TB>>>(0, 0, 0, 0, 0, out);
    // L0it1: read egoS1/Tn8_0/dinvB; write dinvA, egoS0 = acc*dinvA, Tn8_1 = q8(tanh(acc*hinv)); fe->buf1
    k_fused<<<FG, TB>>>(0, 1, 1, 0, 1, out);
    // L1it0: read egoS0/Tn8_1/dinvA; write dinvB, egoS1 = buf1*dinvB
    k_fused<<<FG, TB>>>(1, 0, 0, 1, 0, out);
    // L1it1: final output; read egoS1/dinvB
    k_fused<<<FG, TB>>>(1, 1, 1, 1, 2, out);
    (void)in_sizes; (void)n_in; (void)out_size;
}